// round 3
// baseline (speedup 1.0000x reference)
#include <cuda_runtime.h>
#include <cstdint>

// Problem constants
#define Bz 4
#define Sz 2048
#define Ez 1024
#define Hz 16
#define Dz 64
#define Mrows (Bz*Sz)          // 8192
#define FF (4*Ez)              // 4096

// ---------------------------------------------------------------------------
// Scratch (allocation-free: __device__ globals)
// ---------------------------------------------------------------------------
__device__ float g_Q[(size_t)Mrows*Ez];
__device__ float g_K[(size_t)Mrows*Ez];
__device__ float g_V[(size_t)Mrows*Ez];
__device__ float g_ATT[(size_t)Mrows*Ez];
__device__ float g_X1[(size_t)Mrows*Ez];
__device__ float g_Hb[(size_t)Mrows*FF];

// ---------------------------------------------------------------------------
// Tiled SGEMM: C[M,N] = A[M,K] @ B[K,N]  (+ optional epilogues)
// HEADED: B is stored [H, K, 64] and logical column n = h*64+d
// EPI: 0 = none, 1 = +bias then ReLU, 2 = +bias +res (residual, same shape as C)
// BM=BN=128, BK=8, 256 threads, 8x8 per-thread tile.
// ---------------------------------------------------------------------------
#define BM 128
#define BN 128
#define BK 8
#define TM 8
#define TN 8

template<bool HEADED, int EPI>
__global__ void __launch_bounds__(256)
sgemm_kernel(const float* __restrict__ A, const float* __restrict__ Bm,
             const float* __restrict__ bias, const float* __restrict__ res,
             float* __restrict__ C, int M, int N, int K)
{
    __shared__ float As[BK][BM];
    __shared__ float Bs[BK][BN];

    const int tid  = threadIdx.x;
    const int row0 = blockIdx.y * BM;
    const int col0 = blockIdx.x * BN;

    // A tile loader: one float4 per thread. arow in [0,128), acol in {0,4}
    const int arow = tid >> 1;
    const int acol = (tid & 1) * 4;
    // B tile loader: one float4 per thread. brow in [0,8), bcol in [0,128) step 4
    const int brow = tid >> 5;
    const int bcol = (tid & 31) * 4;

    const int tx = tid & 15;   // N direction
    const int ty = tid >> 4;   // M direction

    float acc[TM][TN];
    #pragma unroll
    for (int i = 0; i < TM; i++)
        #pragma unroll
        for (int j = 0; j < TN; j++) acc[i][j] = 0.f;

    const float* Aptr = A + (size_t)(row0 + arow) * K + acol;

    // HEADED B addressing precompute
    int hh = 0, dd0 = 0;
    if (HEADED) {
        int n = col0 + bcol;
        hh  = n >> 6;
        dd0 = n & 63;
    }

    for (int k0 = 0; k0 < K; k0 += BK) {
        // ---- load A tile (transposed into As) ----
        float4 av = *(const float4*)(Aptr + k0);
        As[acol + 0][arow] = av.x;
        As[acol + 1][arow] = av.y;
        As[acol + 2][arow] = av.z;
        As[acol + 3][arow] = av.w;

        // ---- load B tile ----
        float4 bv;
        if (HEADED) {
            bv = *(const float4*)(Bm + ((size_t)hh * K + (k0 + brow)) * 64 + dd0);
        } else {
            bv = *(const float4*)(Bm + (size_t)(k0 + brow) * N + col0 + bcol);
        }
        *(float4*)(&Bs[brow][bcol]) = bv;

        __syncthreads();

        #pragma unroll
        for (int kk = 0; kk < BK; kk++) {
            float ar[TM], br[TN];
            #pragma unroll
            for (int i = 0; i < TM; i += 4)
                *(float4*)&ar[i] = *(const float4*)&As[kk][ty * TM + i];
            #pragma unroll
            for (int j = 0; j < TN; j += 4)
                *(float4*)&br[j] = *(const float4*)&Bs[kk][tx * TN + j];
            #pragma unroll
            for (int i = 0; i < TM; i++)
                #pragma unroll
                for (int j = 0; j < TN; j++)
                    acc[i][j] += ar[i] * br[j];
        }
        __syncthreads();
    }

    // ---- epilogue ----
    #pragma unroll
    for (int i = 0; i < TM; i++) {
        const int r = row0 + ty * TM + i;
        float* crow = C + (size_t)r * N;
        const float* rrow = (EPI == 2) ? (res + (size_t)r * N) : nullptr;
        #pragma unroll
        for (int j = 0; j < TN; j += 4) {
            const int c = col0 + tx * TN + j;
            float4 v;
            v.x = acc[i][j + 0];
            v.y = acc[i][j + 1];
            v.z = acc[i][j + 2];
            v.w = acc[i][j + 3];
            if (EPI != 0) {
                float4 bb = *(const float4*)(bias + c);
                v.x += bb.x; v.y += bb.y; v.z += bb.z; v.w += bb.w;
            }
            if (EPI == 2) {
                float4 rv = *(const float4*)(rrow + c);
                v.x += rv.x; v.y += rv.y; v.z += rv.z; v.w += rv.w;
            }
            if (EPI == 1) {
                v.x = fmaxf(v.x, 0.f); v.y = fmaxf(v.y, 0.f);
                v.z = fmaxf(v.z, 0.f); v.w = fmaxf(v.w, 0.f);
            }
            *(float4*)(crow + c) = v;
        }
    }
}

// ---------------------------------------------------------------------------
// Causal flash attention, fp32. Q/K/V/O laid out [B, S, H*D] (token-major).
// One query row per thread, 128 rows per block, 32-key smem tiles.
// scale = E^-0.5 = 1/32 (matches reference: e**-0.5 with e = embedding size).
// ---------------------------------------------------------------------------
#define FBN 32

__global__ void __launch_bounds__(128)
flash_kernel(const float* __restrict__ Q, const float* __restrict__ Kg,
             const float* __restrict__ Vg, float* __restrict__ O)
{
    const int qb = blockIdx.x;          // 0..15  (S / 128)
    const int bh = blockIdx.y;          // 0..63  (B*H)
    const int b  = bh >> 4;
    const int h  = bh & 15;
    const int row = qb * 128 + threadIdx.x;   // global query index within S

    const size_t qoff = ((size_t)(b * Sz + row)) * Ez + h * Dz;

    float4 q4[16];
    {
        const float4* qp = (const float4*)(Q + qoff);
        #pragma unroll
        for (int i = 0; i < 16; i++) q4[i] = qp[i];
        const float scale = 0.03125f;   // 1/sqrt(1024)
        #pragma unroll
        for (int i = 0; i < 16; i++) {
            q4[i].x *= scale; q4[i].y *= scale;
            q4[i].z *= scale; q4[i].w *= scale;
        }
    }

    float4 o4[16];
    #pragma unroll
    for (int i = 0; i < 16; i++) o4[i] = make_float4(0.f, 0.f, 0.f, 0.f);
    float m = -1e9f, l = 0.f;

    __shared__ float Ks[FBN * Dz];
    __shared__ float Vs[FBN * Dz];

    const int nkb = (qb + 1) * (128 / FBN);   // key blocks covering [0, (qb+1)*128)

    for (int kb = 0; kb < nkb; kb++) {
        __syncthreads();
        // cooperative K/V tile load: 32 rows x 64 floats = 512 float4 each
        const size_t kbase = ((size_t)(b * Sz + kb * FBN)) * Ez + h * Dz;
        #pragma unroll
        for (int t = 0; t < 4; t++) {
            const int slot = threadIdx.x + t * 128;  // 0..511
            const int j = slot >> 4, c = slot & 15;
            ((float4*)Ks)[slot] = *(const float4*)(Kg + kbase + (size_t)j * Ez + c * 4);
            ((float4*)Vs)[slot] = *(const float4*)(Vg + kbase + (size_t)j * Ez + c * 4);
        }
        __syncthreads();

        const int jmax = row - kb * FBN;  // valid keys: j <= jmax
        float s[FBN];
        #pragma unroll
        for (int j = 0; j < FBN; j++) {
            const float4* kv = (const float4*)(Ks + j * Dz);
            float a0 = 0.f, a1 = 0.f;
            #pragma unroll
            for (int dd = 0; dd < 16; dd += 2) {
                float4 k0 = kv[dd], k1 = kv[dd + 1];
                a0 += q4[dd].x * k0.x + q4[dd].y * k0.y + q4[dd].z * k0.z + q4[dd].w * k0.w;
                a1 += q4[dd+1].x * k1.x + q4[dd+1].y * k1.y + q4[dd+1].z * k1.z + q4[dd+1].w * k1.w;
            }
            s[j] = (j <= jmax) ? (a0 + a1) : -1e9f;
        }

        float mb = m;
        #pragma unroll
        for (int j = 0; j < FBN; j++) mb = fmaxf(mb, s[j]);
        const float corr = __expf(m - mb);
        m = mb;
        l *= corr;
        #pragma unroll
        for (int i = 0; i < 16; i++) {
            o4[i].x *= corr; o4[i].y *= corr; o4[i].z *= corr; o4[i].w *= corr;
        }

        #pragma unroll
        for (int j = 0; j < FBN; j++) {
            const float p = __expf(s[j] - m);
            l += p;
            const float4* vv = (const float4*)(Vs + j * Dz);
            #pragma unroll
            for (int dd = 0; dd < 16; dd++) {
                float4 v4 = vv[dd];
                o4[dd].x += p * v4.x; o4[dd].y += p * v4.y;
                o4[dd].z += p * v4.z; o4[dd].w += p * v4.w;
            }
        }
    }

    const float inv = 1.f / l;
    float4* op = (float4*)(O + qoff);
    #pragma unroll
    for (int i = 0; i < 16; i++) {
        o4[i].x *= inv; o4[i].y *= inv; o4[i].z *= inv; o4[i].w *= inv;
        op[i] = o4[i];
    }
}

// ---------------------------------------------------------------------------
// Launch
// ---------------------------------------------------------------------------
extern "C" void kernel_launch(void* const* d_in, const int* in_sizes, int n_in,
                              void* d_out, int out_size)
{
    const float* x  = (const float*)d_in[0];
    const float* Wq = (const float*)d_in[1];
    const float* Wk = (const float*)d_in[2];
    const float* Wv = (const float*)d_in[3];
    const float* Wo = (const float*)d_in[4];
    const float* bo = (const float*)d_in[5];
    const float* W1 = (const float*)d_in[6];
    const float* b1 = (const float*)d_in[7];
    const float* W2 = (const float*)d_in[8];
    const float* b2 = (const float*)d_in[9];
    float* out = (float*)d_out;

    float *Qp, *Kp, *Vp, *ATTp, *X1p, *Hp;
    cudaGetSymbolAddress((void**)&Qp,   g_Q);
    cudaGetSymbolAddress((void**)&Kp,   g_K);
    cudaGetSymbolAddress((void**)&Vp,   g_V);
    cudaGetSymbolAddress((void**)&ATTp, g_ATT);
    cudaGetSymbolAddress((void**)&X1p,  g_X1);
    cudaGetSymbolAddress((void**)&Hp,   g_Hb);

    const dim3 blk(256);
    const dim3 grid_e(Ez / BN, Mrows / BM);   // (8, 64)
    const dim3 grid_f(FF / BN, Mrows / BM);   // (32, 64)

    // 1-3: per-head QKV projections (weights in [H,E,D] layout)
    sgemm_kernel<true, 0><<<grid_e, blk>>>(x, Wq, nullptr, nullptr, Qp, Mrows, Ez, Ez);
    sgemm_kernel<true, 0><<<grid_e, blk>>>(x, Wk, nullptr, nullptr, Kp, Mrows, Ez, Ez);
    sgemm_kernel<true, 0><<<grid_e, blk>>>(x, Wv, nullptr, nullptr, Vp, Mrows, Ez, Ez);

    // 4: causal flash attention
    flash_kernel<<<dim3(Sz / 128, Bz * Hz), 128>>>(Qp, Kp, Vp, ATTp);

    // 5: x1 = attn @ Wo + bo + x
    sgemm_kernel<false, 2><<<grid_e, blk>>>(ATTp, Wo, bo, x, X1p, Mrows, Ez, Ez);

    // 6: h = relu(x1 @ W1 + b1)
    sgemm_kernel<false, 1><<<grid_f, blk>>>(X1p, W1, b1, nullptr, Hp, Mrows, FF, Ez);

    // 7: out = x1 + h @ W2 + b2
    sgemm_kernel<false, 2><<<grid_e, blk>>>(Hp, W2, b2, X1p, out, Mrows, Ez, FF);
}

// round 4
// speedup vs baseline: 1.7804x; 1.7804x over previous
#include <cuda_runtime.h>
#include <cstdint>

// Problem constants
#define Bz 4
#define Sz 2048
#define Ez 1024
#define Hz 16
#define Dz 64
#define Mrows (Bz*Sz)          // 8192
#define FF (4*Ez)              // 4096

// ---------------------------------------------------------------------------
// Scratch (allocation-free: __device__ globals)
// ---------------------------------------------------------------------------
__device__ float g_Q[(size_t)Mrows*Ez];
__device__ float g_K[(size_t)Mrows*Ez];
__device__ float g_V[(size_t)Mrows*Ez];
__device__ float g_ATT[(size_t)Mrows*Ez];
__device__ float g_X1[(size_t)Mrows*Ez];
__device__ float g_Hb[(size_t)Mrows*FF];

// ---------------------------------------------------------------------------
// TF32 tensor-core GEMM: C[M,N] = A[M,K] @ B[K,N] (+ epilogues)
// mma.sync.aligned.m16n8k8.row.col.f32.tf32.tf32.f32
// Block tile 128x128, BK=16, 256 threads (8 warps), warp tile 32x64.
// Double-buffered smem; fp32 -> tf32 (round-to-nearest) at smem store.
// HEADED: B stored [H, K, 64], logical column n = h*64 + d.
// EPI: 0 none, 1 +bias+ReLU, 2 +bias+residual
// ---------------------------------------------------------------------------
#define LDA 18     // 16 + 2 pad  (A fragment LDS: bank = (18*g + t) % 32, conflict-free-ish)
#define LDB 136    // 128 + 8 pad (B fragment LDS: bank = (8*t + g) % 32, fully conflict-free)

__device__ __forceinline__ uint32_t f2tf(float x) {
    uint32_t u;
    asm("cvt.rna.tf32.f32 %0, %1;" : "=r"(u) : "f"(x));
    return u;
}

#define MMA_TF32(d, a, b0_, b1_)                                            \
    asm volatile(                                                           \
        "mma.sync.aligned.m16n8k8.row.col.f32.tf32.tf32.f32 "               \
        "{%0,%1,%2,%3}, {%4,%5,%6,%7}, {%8,%9}, {%0,%1,%2,%3};"             \
        : "+f"(d[0]), "+f"(d[1]), "+f"(d[2]), "+f"(d[3])                    \
        : "r"(a[0]), "r"(a[1]), "r"(a[2]), "r"(a[3]), "r"(b0_), "r"(b1_))

template<bool HEADED, int EPI>
__global__ void __launch_bounds__(256)
mma_gemm(const float* __restrict__ A, const float* __restrict__ Bm,
         const float* __restrict__ bias, const float* __restrict__ res,
         float* __restrict__ C, int N, int K)
{
    __shared__ uint32_t As[2][128 * LDA];
    __shared__ uint32_t Bs[2][16 * LDB];

    const int tid  = threadIdx.x;
    const int lane = tid & 31;
    const int g    = lane >> 2;     // 0..7
    const int t    = lane & 3;      // 0..3
    const int warp = tid >> 5;      // 0..7
    const int wm   = (warp & 3) * 32;   // warp row offset within block tile
    const int wn   = (warp >> 2) * 64;  // warp col offset within block tile

    const int row0 = blockIdx.y * 128;
    const int col0 = blockIdx.x * 128;

    // gmem tile loader mapping (each thread: 2 float4 of A, 2 float4 of B)
    const int ar = tid >> 2;           // 0..63   (A rows ar, ar+64)
    const int ak = (tid & 3) * 4;      // 0,4,8,12
    const int br = tid >> 5;           // 0..7    (B k-rows br, br+8)
    const int bc = (tid & 31) * 4;     // 0..124

    const float* Ag0 = A + (size_t)(row0 + ar) * K + ak;
    const float* Ag1 = A + (size_t)(row0 + ar + 64) * K + ak;

    const float* Bg0;
    const float* Bg1;
    size_t bstep;                      // element stride per +1 in k
    if (HEADED) {
        const int n = col0 + bc;
        const int h = n >> 6, d = n & 63;
        Bg0 = Bm + ((size_t)h * K + br) * 64 + d;
        Bg1 = Bm + ((size_t)h * K + br + 8) * 64 + d;
        bstep = 64;
    } else {
        Bg0 = Bm + (size_t)br * N + col0 + bc;
        Bg1 = Bm + (size_t)(br + 8) * N + col0 + bc;
        bstep = (size_t)N;
    }

    float acc[2][8][4];
    #pragma unroll
    for (int mt = 0; mt < 2; mt++)
        #pragma unroll
        for (int nt = 0; nt < 8; nt++)
            #pragma unroll
            for (int i = 0; i < 4; i++) acc[mt][nt][i] = 0.f;

    const int nkt = K / 16;

    float4 abuf0, abuf1, bbuf0, bbuf1;

    // ---- prologue: load k-tile 0 ----
    abuf0 = *(const float4*)(Ag0);
    abuf1 = *(const float4*)(Ag1);
    bbuf0 = *(const float4*)(Bg0);
    bbuf1 = *(const float4*)(Bg1);
    {
        uint32_t* as = As[0];
        uint32_t* bs = Bs[0];
        as[ar * LDA + ak + 0] = f2tf(abuf0.x);
        as[ar * LDA + ak + 1] = f2tf(abuf0.y);
        as[ar * LDA + ak + 2] = f2tf(abuf0.z);
        as[ar * LDA + ak + 3] = f2tf(abuf0.w);
        as[(ar + 64) * LDA + ak + 0] = f2tf(abuf1.x);
        as[(ar + 64) * LDA + ak + 1] = f2tf(abuf1.y);
        as[(ar + 64) * LDA + ak + 2] = f2tf(abuf1.z);
        as[(ar + 64) * LDA + ak + 3] = f2tf(abuf1.w);
        bs[br * LDB + bc + 0] = f2tf(bbuf0.x);
        bs[br * LDB + bc + 1] = f2tf(bbuf0.y);
        bs[br * LDB + bc + 2] = f2tf(bbuf0.z);
        bs[br * LDB + bc + 3] = f2tf(bbuf0.w);
        bs[(br + 8) * LDB + bc + 0] = f2tf(bbuf1.x);
        bs[(br + 8) * LDB + bc + 1] = f2tf(bbuf1.y);
        bs[(br + 8) * LDB + bc + 2] = f2tf(bbuf1.z);
        bs[(br + 8) * LDB + bc + 3] = f2tf(bbuf1.w);
    }
    __syncthreads();

    for (int kt = 0; kt < nkt; kt++) {
        const int buf = kt & 1;

        // prefetch next k-tile from gmem into registers
        if (kt + 1 < nkt) {
            const size_t ka = (size_t)(kt + 1) * 16;
            abuf0 = *(const float4*)(Ag0 + ka);
            abuf1 = *(const float4*)(Ag1 + ka);
            bbuf0 = *(const float4*)(Bg0 + ka * bstep);
            bbuf1 = *(const float4*)(Bg1 + ka * bstep);
        }

        // compute on current buffer
        const uint32_t* asb = As[buf];
        const uint32_t* bsb = Bs[buf];
        #pragma unroll
        for (int ks = 0; ks < 16; ks += 8) {
            uint32_t af[2][4];
            #pragma unroll
            for (int mt = 0; mt < 2; mt++) {
                const uint32_t* p = asb + (wm + mt * 16 + g) * LDA + ks + t;
                af[mt][0] = p[0];
                af[mt][1] = p[8 * LDA];
                af[mt][2] = p[4];
                af[mt][3] = p[8 * LDA + 4];
            }
            uint32_t bflo[8], bfhi[8];
            #pragma unroll
            for (int nt = 0; nt < 8; nt++) {
                bflo[nt] = bsb[(ks + t) * LDB + wn + nt * 8 + g];
                bfhi[nt] = bsb[(ks + t + 4) * LDB + wn + nt * 8 + g];
            }
            #pragma unroll
            for (int mt = 0; mt < 2; mt++)
                #pragma unroll
                for (int nt = 0; nt < 8; nt++)
                    MMA_TF32(acc[mt][nt], af[mt], bflo[nt], bfhi[nt]);
        }

        // stage next tile into the other buffer
        if (kt + 1 < nkt) {
            uint32_t* as = As[buf ^ 1];
            uint32_t* bs = Bs[buf ^ 1];
            as[ar * LDA + ak + 0] = f2tf(abuf0.x);
            as[ar * LDA + ak + 1] = f2tf(abuf0.y);
            as[ar * LDA + ak + 2] = f2tf(abuf0.z);
            as[ar * LDA + ak + 3] = f2tf(abuf0.w);
            as[(ar + 64) * LDA + ak + 0] = f2tf(abuf1.x);
            as[(ar + 64) * LDA + ak + 1] = f2tf(abuf1.y);
            as[(ar + 64) * LDA + ak + 2] = f2tf(abuf1.z);
            as[(ar + 64) * LDA + ak + 3] = f2tf(abuf1.w);
            bs[br * LDB + bc + 0] = f2tf(bbuf0.x);
            bs[br * LDB + bc + 1] = f2tf(bbuf0.y);
            bs[br * LDB + bc + 2] = f2tf(bbuf0.z);
            bs[br * LDB + bc + 3] = f2tf(bbuf0.w);
            bs[(br + 8) * LDB + bc + 0] = f2tf(bbuf1.x);
            bs[(br + 8) * LDB + bc + 1] = f2tf(bbuf1.y);
            bs[(br + 8) * LDB + bc + 2] = f2tf(bbuf1.z);
            bs[(br + 8) * LDB + bc + 3] = f2tf(bbuf1.w);
            __syncthreads();
        }
    }

    // ---- epilogue ----
    #pragma unroll
    for (int mt = 0; mt < 2; mt++) {
        #pragma unroll
        for (int nt = 0; nt < 8; nt++) {
            const int r = row0 + wm + mt * 16 + g;
            const int c = col0 + wn + nt * 8 + 2 * t;
            float2 v0 = make_float2(acc[mt][nt][0], acc[mt][nt][1]);
            float2 v1 = make_float2(acc[mt][nt][2], acc[mt][nt][3]);
            if (EPI != 0) {
                const float2 bb = *(const float2*)(bias + c);
                v0.x += bb.x; v0.y += bb.y;
                v1.x += bb.x; v1.y += bb.y;
            }
            if (EPI == 2) {
                const float2 r0v = *(const float2*)(res + (size_t)r * N + c);
                const float2 r1v = *(const float2*)(res + (size_t)(r + 8) * N + c);
                v0.x += r0v.x; v0.y += r0v.y;
                v1.x += r1v.x; v1.y += r1v.y;
            }
            if (EPI == 1) {
                v0.x = fmaxf(v0.x, 0.f); v0.y = fmaxf(v0.y, 0.f);
                v1.x = fmaxf(v1.x, 0.f); v1.y = fmaxf(v1.y, 0.f);
            }
            *(float2*)(C + (size_t)r * N + c) = v0;
            *(float2*)(C + (size_t)(r + 8) * N + c) = v1;
        }
    }
}

// ---------------------------------------------------------------------------
// Causal flash attention, fp32. Q/K/V/O laid out [B, S, H*D] (token-major).
// One query row per thread, 128 rows per block, 32-key smem tiles.
// scale = E^-0.5 = 1/32 (matches reference).
// ---------------------------------------------------------------------------
#define FBN 32

__global__ void __launch_bounds__(128)
flash_kernel(const float* __restrict__ Q, const float* __restrict__ Kg,
             const float* __restrict__ Vg, float* __restrict__ O)
{
    const int qb = blockIdx.x;
    const int bh = blockIdx.y;
    const int b  = bh >> 4;
    const int h  = bh & 15;
    const int row = qb * 128 + threadIdx.x;

    const size_t qoff = ((size_t)(b * Sz + row)) * Ez + h * Dz;

    float4 q4[16];
    {
        const float4* qp = (const float4*)(Q + qoff);
        #pragma unroll
        for (int i = 0; i < 16; i++) q4[i] = qp[i];
        const float scale = 0.03125f;
        #pragma unroll
        for (int i = 0; i < 16; i++) {
            q4[i].x *= scale; q4[i].y *= scale;
            q4[i].z *= scale; q4[i].w *= scale;
        }
    }

    float4 o4[16];
    #pragma unroll
    for (int i = 0; i < 16; i++) o4[i] = make_float4(0.f, 0.f, 0.f, 0.f);
    float m = -1e9f, l = 0.f;

    __shared__ float Ks[FBN * Dz];
    __shared__ float Vs[FBN * Dz];

    const int nkb = (qb + 1) * (128 / FBN);

    for (int kb = 0; kb < nkb; kb++) {
        __syncthreads();
        const size_t kbase = ((size_t)(b * Sz + kb * FBN)) * Ez + h * Dz;
        #pragma unroll
        for (int tt = 0; tt < 4; tt++) {
            const int slot = threadIdx.x + tt * 128;
            const int j = slot >> 4, c = slot & 15;
            ((float4*)Ks)[slot] = *(const float4*)(Kg + kbase + (size_t)j * Ez + c * 4);
            ((float4*)Vs)[slot] = *(const float4*)(Vg + kbase + (size_t)j * Ez + c * 4);
        }
        __syncthreads();

        const int jmax = row - kb * FBN;
        float s[FBN];
        #pragma unroll
        for (int j = 0; j < FBN; j++) {
            const float4* kv = (const float4*)(Ks + j * Dz);
            float a0 = 0.f, a1 = 0.f;
            #pragma unroll
            for (int dd = 0; dd < 16; dd += 2) {
                float4 k0 = kv[dd], k1 = kv[dd + 1];
                a0 += q4[dd].x * k0.x + q4[dd].y * k0.y + q4[dd].z * k0.z + q4[dd].w * k0.w;
                a1 += q4[dd+1].x * k1.x + q4[dd+1].y * k1.y + q4[dd+1].z * k1.z + q4[dd+1].w * k1.w;
            }
            s[j] = (j <= jmax) ? (a0 + a1) : -1e9f;
        }

        float mb = m;
        #pragma unroll
        for (int j = 0; j < FBN; j++) mb = fmaxf(mb, s[j]);
        const float corr = __expf(m - mb);
        m = mb;
        l *= corr;
        #pragma unroll
        for (int i = 0; i < 16; i++) {
            o4[i].x *= corr; o4[i].y *= corr; o4[i].z *= corr; o4[i].w *= corr;
        }

        #pragma unroll
        for (int j = 0; j < FBN; j++) {
            const float p = __expf(s[j] - m);
            l += p;
            const float4* vv = (const float4*)(Vs + j * Dz);
            #pragma unroll
            for (int dd = 0; dd < 16; dd++) {
                float4 v4 = vv[dd];
                o4[dd].x += p * v4.x; o4[dd].y += p * v4.y;
                o4[dd].z += p * v4.z; o4[dd].w += p * v4.w;
            }
        }
    }

    const float inv = 1.f / l;
    float4* op = (float4*)(O + qoff);
    #pragma unroll
    for (int i = 0; i < 16; i++) {
        o4[i].x *= inv; o4[i].y *= inv; o4[i].z *= inv; o4[i].w *= inv;
        op[i] = o4[i];
    }
}

// ---------------------------------------------------------------------------
// Launch
// ---------------------------------------------------------------------------
extern "C" void kernel_launch(void* const* d_in, const int* in_sizes, int n_in,
                              void* d_out, int out_size)
{
    const float* x  = (const float*)d_in[0];
    const float* Wq = (const float*)d_in[1];
    const float* Wk = (const float*)d_in[2];
    const float* Wv = (const float*)d_in[3];
    const float* Wo = (const float*)d_in[4];
    const float* bo = (const float*)d_in[5];
    const float* W1 = (const float*)d_in[6];
    const float* b1 = (const float*)d_in[7];
    const float* W2 = (const float*)d_in[8];
    const float* b2 = (const float*)d_in[9];
    float* out = (float*)d_out;

    float *Qp, *Kp, *Vp, *ATTp, *X1p, *Hp;
    cudaGetSymbolAddress((void**)&Qp,   g_Q);
    cudaGetSymbolAddress((void**)&Kp,   g_K);
    cudaGetSymbolAddress((void**)&Vp,   g_V);
    cudaGetSymbolAddress((void**)&ATTp, g_ATT);
    cudaGetSymbolAddress((void**)&X1p,  g_X1);
    cudaGetSymbolAddress((void**)&Hp,   g_Hb);

    const dim3 blk(256);
    const dim3 grid_e(Ez / 128, Mrows / 128);   // (8, 64)
    const dim3 grid_f(FF / 128, Mrows / 128);   // (32, 64)

    // 1-3: per-head QKV projections (weights in [H,E,D] layout)
    mma_gemm<true, 0><<<grid_e, blk>>>(x, Wq, nullptr, nullptr, Qp, Ez, Ez);
    mma_gemm<true, 0><<<grid_e, blk>>>(x, Wk, nullptr, nullptr, Kp, Ez, Ez);
    mma_gemm<true, 0><<<grid_e, blk>>>(x, Wv, nullptr, nullptr, Vp, Ez, Ez);

    // 4: causal flash attention
    flash_kernel<<<dim3(Sz / 128, Bz * Hz), 128>>>(Qp, Kp, Vp, ATTp);

    // 5: x1 = attn @ Wo + bo + x
    mma_gemm<false, 2><<<grid_e, blk>>>(ATTp, Wo, bo, x, X1p, Ez, Ez);

    // 6: h = relu(x1 @ W1 + b1)
    mma_gemm<false, 1><<<grid_f, blk>>>(X1p, W1, b1, nullptr, Hp, FF, Ez);

    // 7: out = x1 + h @ W2 + b2
    mma_gemm<false, 2><<<grid_e, blk>>>(Hp, W2, b2, X1p, out, Ez, FF);
}

// round 6
// speedup vs baseline: 1.8493x; 1.0387x over previous
#include <cuda_runtime.h>
#include <cstdint>

// Problem constants
#define Bz 4
#define Sz 2048
#define Ez 1024
#define Hz 16
#define Dz 64
#define Mrows (Bz*Sz)          // 8192
#define FF (4*Ez)              // 4096

// ---------------------------------------------------------------------------
// Scratch (allocation-free: __device__ globals)
// ---------------------------------------------------------------------------
__device__ float    g_Q  [(size_t)Mrows*Ez];
__device__ float    g_K  [(size_t)Mrows*Ez];
__device__ float    g_V  [(size_t)Mrows*Ez];
__device__ uint32_t g_ATT[(size_t)Mrows*Ez];     // tf32 bits (flash output)
__device__ float    g_X1 [(size_t)Mrows*Ez];     // fp32 (residual for final)
__device__ uint32_t g_X1T[(size_t)Mrows*Ez];     // tf32 bits (A of W1 gemm)
__device__ uint32_t g_Hb [(size_t)Mrows*FF];     // tf32 bits (A of W2 gemm)
__device__ uint32_t g_xT [(size_t)Mrows*Ez];     // tf32 bits of x
// transposed tf32 weights, layout [N, K]
__device__ uint32_t g_WqT[(size_t)Ez*Ez];
__device__ uint32_t g_WkT[(size_t)Ez*Ez];
__device__ uint32_t g_WvT[(size_t)Ez*Ez];
__device__ uint32_t g_WoT[(size_t)Ez*Ez];
__device__ uint32_t g_W1T[(size_t)FF*Ez];
__device__ uint32_t g_W2T[(size_t)Ez*FF];

// ---------------------------------------------------------------------------
// Helpers
// ---------------------------------------------------------------------------
__device__ __forceinline__ uint32_t f2tf(float x) {
    uint32_t u;
    asm("cvt.rna.tf32.f32 %0, %1;" : "=r"(u) : "f"(x));
    return u;
}

__device__ __forceinline__ uint32_t smem_u32(const void* p) {
    uint32_t a;
    asm("{ .reg .u64 t; cvta.to.shared.u64 t, %1; cvt.u32.u64 %0, t; }"
        : "=r"(a) : "l"(p));
    return a;
}

#define CP_ASYNC16(dst, src) \
    asm volatile("cp.async.cg.shared.global [%0], [%1], 16;" :: "r"(dst), "l"(src))
#define CP_COMMIT() asm volatile("cp.async.commit_group;" ::: "memory")
#define CP_WAIT(n)  asm volatile("cp.async.wait_group %0;" :: "n"(n) : "memory")

#define MMA_TF32(d, a, b0_, b1_)                                            \
    asm volatile(                                                           \
        "mma.sync.aligned.m16n8k8.row.col.f32.tf32.tf32.f32 "               \
        "{%0,%1,%2,%3}, {%4,%5,%6,%7}, {%8,%9}, {%0,%1,%2,%3};"             \
        : "+f"(d[0]), "+f"(d[1]), "+f"(d[2]), "+f"(d[3])                    \
        : "r"(a[0]), "r"(a[1]), "r"(a[2]), "r"(a[3]), "r"(b0_), "r"(b1_))

// ---------------------------------------------------------------------------
// fp32 -> tf32 bits elementwise convert (for x)
// ---------------------------------------------------------------------------
__global__ void __launch_bounds__(256)
conv_tf32_kernel(const float4* __restrict__ in, uint4* __restrict__ out, int n4)
{
    const int i = blockIdx.x * 256 + threadIdx.x;
    if (i < n4) {
        const float4 v = in[i];
        uint4 u;
        u.x = f2tf(v.x); u.y = f2tf(v.y); u.z = f2tf(v.z); u.w = f2tf(v.w);
        out[i] = u;
    }
}

// ---------------------------------------------------------------------------
// Weight transpose + tf32 convert:  W[k,n] -> Wt[n*K + k] (tf32 bits)
// HEADED: input stored [H, K, 64], logical n = h*64 + d
// ---------------------------------------------------------------------------
template<bool HEADED>
__global__ void __launch_bounds__(256)
transpose_tf32(const float* __restrict__ W, uint32_t* __restrict__ Wt, int K, int N)
{
    __shared__ uint32_t tile[32][33];
    const int k0 = blockIdx.x * 32, n0 = blockIdx.y * 32;
    const int tx = threadIdx.x & 31, ty = threadIdx.x >> 5;   // 32 x 8
    #pragma unroll
    for (int r = 0; r < 32; r += 8) {
        const int k = k0 + ty + r, n = n0 + tx;
        float v;
        if (HEADED) v = W[((size_t)(n >> 6) * K + k) * 64 + (n & 63)];
        else        v = W[(size_t)k * N + n];
        tile[ty + r][tx] = f2tf(v);
    }
    __syncthreads();
    #pragma unroll
    for (int r = 0; r < 32; r += 8) {
        const int n = n0 + ty + r, k = k0 + tx;
        Wt[(size_t)n * K + k] = tile[tx][ty + r];
    }
}

// ---------------------------------------------------------------------------
// TF32 tensor-core GEMM: C[M,N] = A[M,K] @ Bt[N,K]^T  (+ epilogues)
// A, Bt: tf32 bits, K-major. Block tile 128(m) x 256(n), BK=16, 256 threads,
// 8 warps of 64x64, cp.async double-buffered smem, padded stride 20.
// EPI: 0 none, 1 +bias+ReLU, 2 +bias+residual(fp32)
// OMODE: 0 fp32 out, 1 tf32 out, 2 both
// ---------------------------------------------------------------------------
#define AST 20                      // smem row stride in words (16 + 4 pad)
#define A_WORDS (128 * AST)         // 2560 words / buffer
#define B_WORDS (256 * AST)         // 5120 words / buffer
#define GEMM_SMEM_BYTES ((A_WORDS * 2 + B_WORDS * 2) * 4)   // 61440

template<int EPI, int OMODE>
__global__ void __launch_bounds__(256, 1)
mma_gemm(const uint32_t* __restrict__ A, const uint32_t* __restrict__ Bt,
         const float* __restrict__ bias, const float* __restrict__ res,
         float* __restrict__ Cf, uint32_t* __restrict__ Ct, int N, int K)
{
    extern __shared__ uint32_t smw[];
    const uint32_t sb = smem_u32(smw);

    const int tid  = threadIdx.x;
    const int lane = tid & 31;
    const int g    = lane >> 2;          // 0..7
    const int t    = lane & 3;           // 0..3
    const int warp = tid >> 5;           // 0..7
    const int wm   = (warp & 1) * 64;    // 2 warps in m
    const int wn   = (warp >> 1) * 64;   // 4 warps in n

    const int row0 = blockIdx.y * 128;
    const int col0 = blockIdx.x * 256;

    // cp.async loader mapping
    // A: 128 rows x 4 chunks = 512 chunks -> 2 per thread
    // B: 256 rows x 4 chunks = 1024 chunks -> 4 per thread
    int a_row[2], a_c4[2];
    #pragma unroll
    for (int i = 0; i < 2; i++) {
        const int idx = tid + i * 256;
        a_row[i] = idx >> 2; a_c4[i] = idx & 3;
    }
    int b_row[4], b_c4[4];
    #pragma unroll
    for (int i = 0; i < 4; i++) {
        const int idx = tid + i * 256;
        b_row[i] = idx >> 2; b_c4[i] = idx & 3;
    }

    const uint32_t sA[2] = { sb, sb + A_WORDS * 4 };
    const uint32_t sB[2] = { sb + A_WORDS * 8, sb + A_WORDS * 8 + B_WORDS * 4 };

    const int nkt = K / 16;

    // tile loader
    auto load_tile = [&](int kt, int buf) {
        const int kk = kt * 16;
        #pragma unroll
        for (int i = 0; i < 2; i++) {
            const uint32_t dst = sA[buf] + (uint32_t)(a_row[i] * AST + a_c4[i] * 4) * 4;
            const uint32_t* src = A + (size_t)(row0 + a_row[i]) * K + kk + a_c4[i] * 4;
            CP_ASYNC16(dst, src);
        }
        #pragma unroll
        for (int i = 0; i < 4; i++) {
            const uint32_t dst = sB[buf] + (uint32_t)(b_row[i] * AST + b_c4[i] * 4) * 4;
            const uint32_t* src = Bt + (size_t)(col0 + b_row[i]) * K + kk + b_c4[i] * 4;
            CP_ASYNC16(dst, src);
        }
        CP_COMMIT();
    };

    float acc[4][8][4];
    #pragma unroll
    for (int mt = 0; mt < 4; mt++)
        #pragma unroll
        for (int nt = 0; nt < 8; nt++)
            #pragma unroll
            for (int i = 0; i < 4; i++) acc[mt][nt][i] = 0.f;

    load_tile(0, 0);

    for (int kt = 0; kt < nkt; kt++) {
        const int buf = kt & 1;
        if (kt + 1 < nkt) {
            load_tile(kt + 1, buf ^ 1);
            CP_WAIT(1);
        } else {
            CP_WAIT(0);
        }
        __syncthreads();

        const uint32_t* As = smw + buf * A_WORDS;
        const uint32_t* Bs = smw + 2 * A_WORDS + buf * B_WORDS;

        #pragma unroll
        for (int ks = 0; ks < 16; ks += 8) {
            uint32_t af[4][4];
            #pragma unroll
            for (int mt = 0; mt < 4; mt++) {
                const uint32_t* p = As + (wm + mt * 16 + g) * AST + ks + t;
                af[mt][0] = p[0];
                af[mt][1] = p[8 * AST];
                af[mt][2] = p[4];
                af[mt][3] = p[8 * AST + 4];
            }
            uint32_t blo[8], bhi[8];
            #pragma unroll
            for (int nt = 0; nt < 8; nt++) {
                const uint32_t* p = Bs + (wn + nt * 8 + g) * AST + ks + t;
                blo[nt] = p[0];
                bhi[nt] = p[4];
            }
            #pragma unroll
            for (int mt = 0; mt < 4; mt++)
                #pragma unroll
                for (int nt = 0; nt < 8; nt++)
                    MMA_TF32(acc[mt][nt], af[mt], blo[nt], bhi[nt]);
        }
        __syncthreads();
    }

    // ---- epilogue ----
    #pragma unroll
    for (int mt = 0; mt < 4; mt++) {
        #pragma unroll
        for (int nt = 0; nt < 8; nt++) {
            const int r = row0 + wm + mt * 16 + g;
            const int c = col0 + wn + nt * 8 + 2 * t;
            float2 v0 = make_float2(acc[mt][nt][0], acc[mt][nt][1]);
            float2 v1 = make_float2(acc[mt][nt][2], acc[mt][nt][3]);
            if (EPI != 0) {
                const float2 bb = *(const float2*)(bias + c);
                v0.x += bb.x; v0.y += bb.y;
                v1.x += bb.x; v1.y += bb.y;
            }
            if (EPI == 2) {
                const float2 r0v = *(const float2*)(res + (size_t)r * N + c);
                const float2 r1v = *(const float2*)(res + (size_t)(r + 8) * N + c);
                v0.x += r0v.x; v0.y += r0v.y;
                v1.x += r1v.x; v1.y += r1v.y;
            }
            if (EPI == 1) {
                v0.x = fmaxf(v0.x, 0.f); v0.y = fmaxf(v0.y, 0.f);
                v1.x = fmaxf(v1.x, 0.f); v1.y = fmaxf(v1.y, 0.f);
            }
            if (OMODE == 0 || OMODE == 2) {
                *(float2*)(Cf + (size_t)r * N + c) = v0;
                *(float2*)(Cf + (size_t)(r + 8) * N + c) = v1;
            }
            if (OMODE == 1 || OMODE == 2) {
                uint2 t0, t1;
                t0.x = f2tf(v0.x); t0.y = f2tf(v0.y);
                t1.x = f2tf(v1.x); t1.y = f2tf(v1.y);
                *(uint2*)(Ct + (size_t)r * N + c) = t0;
                *(uint2*)(Ct + (size_t)(r + 8) * N + c) = t1;
            }
        }
    }
}

// ---------------------------------------------------------------------------
// Causal flash attention, fp32 math; outputs tf32 bits (A of the Wo GEMM).
// scale = E^-0.5 = 1/32 (matches reference).
// ---------------------------------------------------------------------------
#define FBN 32

__global__ void __launch_bounds__(128)
flash_kernel(const float* __restrict__ Q, const float* __restrict__ Kg,
             const float* __restrict__ Vg, uint32_t* __restrict__ O)
{
    const int qb = blockIdx.x;
    const int bh = blockIdx.y;
    const int b  = bh >> 4;
    const int h  = bh & 15;
    const int row = qb * 128 + threadIdx.x;

    const size_t qoff = ((size_t)(b * Sz + row)) * Ez + h * Dz;

    float4 q4[16];
    {
        const float4* qp = (const float4*)(Q + qoff);
        #pragma unroll
        for (int i = 0; i < 16; i++) q4[i] = qp[i];
        const float scale = 0.03125f;
        #pragma unroll
        for (int i = 0; i < 16; i++) {
            q4[i].x *= scale; q4[i].y *= scale;
            q4[i].z *= scale; q4[i].w *= scale;
        }
    }

    float4 o4[16];
    #pragma unroll
    for (int i = 0; i < 16; i++) o4[i] = make_float4(0.f, 0.f, 0.f, 0.f);
    float m = -1e9f, l = 0.f;

    __shared__ float Ks[FBN * Dz];
    __shared__ float Vs[FBN * Dz];

    const int nkb = (qb + 1) * (128 / FBN);

    for (int kb = 0; kb < nkb; kb++) {
        __syncthreads();
        const size_t kbase = ((size_t)(b * Sz + kb * FBN)) * Ez + h * Dz;
        #pragma unroll
        for (int tt = 0; tt < 4; tt++) {
            const int slot = threadIdx.x + tt * 128;
            const int j = slot >> 4, c = slot & 15;
            ((float4*)Ks)[slot] = *(const float4*)(Kg + kbase + (size_t)j * Ez + c * 4);
            ((float4*)Vs)[slot] = *(const float4*)(Vg + kbase + (size_t)j * Ez + c * 4);
        }
        __syncthreads();

        const int jmax = row - kb * FBN;
        float s[FBN];
        #pragma unroll
        for (int j = 0; j < FBN; j++) {
            const float4* kv = (const float4*)(Ks + j * Dz);
            float a0 = 0.f, a1 = 0.f;
            #pragma unroll
            for (int dd = 0; dd < 16; dd += 2) {
                float4 k0 = kv[dd], k1 = kv[dd + 1];
                a0 += q4[dd].x * k0.x + q4[dd].y * k0.y + q4[dd].z * k0.z + q4[dd].w * k0.w;
                a1 += q4[dd+1].x * k1.x + q4[dd+1].y * k1.y + q4[dd+1].z * k1.z + q4[dd+1].w * k1.w;
            }
            s[j] = (j <= jmax) ? (a0 + a1) : -1e9f;
        }

        float mb = m;
        #pragma unroll
        for (int j = 0; j < FBN; j++) mb = fmaxf(mb, s[j]);
        const float corr = __expf(m - mb);
        m = mb;
        l *= corr;
        #pragma unroll
        for (int i = 0; i < 16; i++) {
            o4[i].x *= corr; o4[i].y *= corr; o4[i].z *= corr; o4[i].w *= corr;
        }

        #pragma unroll
        for (int j = 0; j < FBN; j++) {
            const float p = __expf(s[j] - m);
            l += p;
            const float4* vv = (const float4*)(Vs + j * Dz);
            #pragma unroll
            for (int dd = 0; dd < 16; dd++) {
                float4 v4 = vv[dd];
                o4[dd].x += p * v4.x; o4[dd].y += p * v4.y;
                o4[dd].z += p * v4.z; o4[dd].w += p * v4.w;
            }
        }
    }

    const float inv = 1.f / l;
    uint4* op = (uint4*)(O + qoff);
    #pragma unroll
    for (int i = 0; i < 16; i++) {
        uint4 u;
        u.x = f2tf(o4[i].x * inv); u.y = f2tf(o4[i].y * inv);
        u.z = f2tf(o4[i].z * inv); u.w = f2tf(o4[i].w * inv);
        op[i] = u;
    }
}

// ---------------------------------------------------------------------------
// Launch
// ---------------------------------------------------------------------------
extern "C" void kernel_launch(void* const* d_in, const int* in_sizes, int n_in,
                              void* d_out, int out_size)
{
    const float* x  = (const float*)d_in[0];
    const float* Wq = (const float*)d_in[1];
    const float* Wk = (const float*)d_in[2];
    const float* Wv = (const float*)d_in[3];
    const float* Wo = (const float*)d_in[4];
    const float* bo = (const float*)d_in[5];
    const float* W1 = (const float*)d_in[6];
    const float* b1 = (const float*)d_in[7];
    const float* W2 = (const float*)d_in[8];
    const float* b2 = (const float*)d_in[9];
    float* out = (float*)d_out;

    float *Qp, *Kp, *Vp, *X1p;
    uint32_t *ATTp, *X1Tp, *Hp, *xTp;
    uint32_t *WqT, *WkT, *WvT, *WoT, *W1T, *W2T;
    cudaGetSymbolAddress((void**)&Qp,   g_Q);
    cudaGetSymbolAddress((void**)&Kp,   g_K);
    cudaGetSymbolAddress((void**)&Vp,   g_V);
    cudaGetSymbolAddress((void**)&ATTp, g_ATT);
    cudaGetSymbolAddress((void**)&X1p,  g_X1);
    cudaGetSymbolAddress((void**)&X1Tp, g_X1T);
    cudaGetSymbolAddress((void**)&Hp,   g_Hb);
    cudaGetSymbolAddress((void**)&xTp,  g_xT);
    cudaGetSymbolAddress((void**)&WqT,  g_WqT);
    cudaGetSymbolAddress((void**)&WkT,  g_WkT);
    cudaGetSymbolAddress((void**)&WvT,  g_WvT);
    cudaGetSymbolAddress((void**)&WoT,  g_WoT);
    cudaGetSymbolAddress((void**)&W1T,  g_W1T);
    cudaGetSymbolAddress((void**)&W2T,  g_W2T);

    cudaFuncSetAttribute(mma_gemm<0,0>, cudaFuncAttributeMaxDynamicSharedMemorySize, GEMM_SMEM_BYTES);
    cudaFuncSetAttribute(mma_gemm<2,2>, cudaFuncAttributeMaxDynamicSharedMemorySize, GEMM_SMEM_BYTES);
    cudaFuncSetAttribute(mma_gemm<1,1>, cudaFuncAttributeMaxDynamicSharedMemorySize, GEMM_SMEM_BYTES);
    cudaFuncSetAttribute(mma_gemm<2,0>, cudaFuncAttributeMaxDynamicSharedMemorySize, GEMM_SMEM_BYTES);

    const dim3 tblk(256);

    // 0a: x -> tf32 bits
    conv_tf32_kernel<<<(Mrows * Ez / 4 + 255) / 256, tblk>>>((const float4*)x, (uint4*)xTp, Mrows * Ez / 4);

    // 0b: weight transposes (+ tf32 convert), output [N,K]
    transpose_tf32<true ><<<dim3(Ez / 32, Ez / 32), tblk>>>(Wq, WqT, Ez, Ez);
    transpose_tf32<true ><<<dim3(Ez / 32, Ez / 32), tblk>>>(Wk, WkT, Ez, Ez);
    transpose_tf32<true ><<<dim3(Ez / 32, Ez / 32), tblk>>>(Wv, WvT, Ez, Ez);
    transpose_tf32<false><<<dim3(Ez / 32, Ez / 32), tblk>>>(Wo, WoT, Ez, Ez);
    transpose_tf32<false><<<dim3(Ez / 32, FF / 32), tblk>>>(W1, W1T, Ez, FF);
    transpose_tf32<false><<<dim3(FF / 32, Ez / 32), tblk>>>(W2, W2T, FF, Ez);

    const dim3 grid_e(Ez / 256, Mrows / 128);   // (4, 64)
    const dim3 grid_f(FF / 256, Mrows / 128);   // (16, 64)

    // 1-3: QKV projections (fp32 out for flash)
    mma_gemm<0,0><<<grid_e, tblk, GEMM_SMEM_BYTES>>>(xTp, WqT, nullptr, nullptr, Qp, nullptr, Ez, Ez);
    mma_gemm<0,0><<<grid_e, tblk, GEMM_SMEM_BYTES>>>(xTp, WkT, nullptr, nullptr, Kp, nullptr, Ez, Ez);
    mma_gemm<0,0><<<grid_e, tblk, GEMM_SMEM_BYTES>>>(xTp, WvT, nullptr, nullptr, Vp, nullptr, Ez, Ez);

    // 4: causal flash attention (tf32 out)
    flash_kernel<<<dim3(Sz / 128, Bz * Hz), 128>>>(Qp, Kp, Vp, ATTp);

    // 5: x1 = attn @ Wo + bo + x  (fp32 + tf32 out)
    mma_gemm<2,2><<<grid_e, tblk, GEMM_SMEM_BYTES>>>(ATTp, WoT, bo, x, X1p, X1Tp, Ez, Ez);

    // 6: h = relu(x1 @ W1 + b1)  (tf32 out)
    mma_gemm<1,1><<<grid_f, tblk, GEMM_SMEM_BYTES>>>(X1Tp, W1T, b1, nullptr, nullptr, Hp, FF, Ez);

    // 7: out = x1 + h @ W2 + b2  (fp32 out)
    mma_gemm<2,0><<<grid_e, tblk, GEMM_SMEM_BYTES>>>(Hp, W2T, b2, X1p, out, nullptr, Ez, FF);
}

// round 7
// speedup vs baseline: 6.4521x; 3.4889x over previous
#include <cuda_runtime.h>
#include <cuda_fp16.h>
#include <cstdint>

// Problem constants
#define Bz 4
#define Sz 2048
#define Ez 1024
#define Hz 16
#define Dz 64
#define Mrows (Bz*Sz)          // 8192
#define FF (4*Ez)              // 4096

// ---------------------------------------------------------------------------
// Scratch (allocation-free: __device__ globals) — all operands fp16
// ---------------------------------------------------------------------------
__device__ __half g_Qh [(size_t)Mrows*Ez];
__device__ __half g_Kh [(size_t)Mrows*Ez];
__device__ __half g_Vh [(size_t)Mrows*Ez];
__device__ __half g_ATT[(size_t)Mrows*Ez];
__device__ float  g_X1 [(size_t)Mrows*Ez];      // fp32 residual
__device__ __half g_X1h[(size_t)Mrows*Ez];
__device__ __half g_Hh [(size_t)Mrows*FF];
__device__ __half g_xh [(size_t)Mrows*Ez];
// transposed fp16 weights, layout [N, K]
__device__ __half g_WqT[(size_t)Ez*Ez];
__device__ __half g_WkT[(size_t)Ez*Ez];
__device__ __half g_WvT[(size_t)Ez*Ez];
__device__ __half g_WoT[(size_t)Ez*Ez];
__device__ __half g_W1T[(size_t)FF*Ez];
__device__ __half g_W2T[(size_t)Ez*FF];

// ---------------------------------------------------------------------------
// Helpers
// ---------------------------------------------------------------------------
__device__ __forceinline__ uint32_t smem_u32(const void* p) {
    uint32_t a;
    asm("{ .reg .u64 t; cvta.to.shared.u64 t, %1; cvt.u32.u64 %0, t; }"
        : "=r"(a) : "l"(p));
    return a;
}

#define CP_ASYNC16(dst, src) \
    asm volatile("cp.async.cg.shared.global [%0], [%1], 16;" :: "r"(dst), "l"(src))
#define CP_COMMIT() asm volatile("cp.async.commit_group;" ::: "memory")
#define CP_WAIT(n)  asm volatile("cp.async.wait_group %0;" :: "n"(n) : "memory")

#define MMA_F16(d, a0_, a1_, a2_, a3_, b0_, b1_)                            \
    asm volatile(                                                           \
        "mma.sync.aligned.m16n8k16.row.col.f32.f16.f16.f32 "                \
        "{%0,%1,%2,%3}, {%4,%5,%6,%7}, {%8,%9}, {%0,%1,%2,%3};"             \
        : "+f"((d)[0]), "+f"((d)[1]), "+f"((d)[2]), "+f"((d)[3])            \
        : "r"(a0_), "r"(a1_), "r"(a2_), "r"(a3_), "r"(b0_), "r"(b1_))

#define LDSM4(r0, r1, r2, r3, addr)                                         \
    asm volatile("ldmatrix.sync.aligned.m8n8.x4.shared.b16 {%0,%1,%2,%3}, [%4];" \
        : "=r"(r0), "=r"(r1), "=r"(r2), "=r"(r3) : "r"(addr))

#define LDSM4T(r0, r1, r2, r3, addr)                                        \
    asm volatile("ldmatrix.sync.aligned.m8n8.x4.trans.shared.b16 {%0,%1,%2,%3}, [%4];" \
        : "=r"(r0), "=r"(r1), "=r"(r2), "=r"(r3) : "r"(addr))

// ---------------------------------------------------------------------------
// fp32 -> fp16 elementwise convert (for x)
// ---------------------------------------------------------------------------
__global__ void __launch_bounds__(256)
conv_h_kernel(const float4* __restrict__ in, uint2* __restrict__ out, int n4)
{
    const int i = blockIdx.x * 256 + threadIdx.x;
    if (i < n4) {
        const float4 v = in[i];
        __half2 lo = __float22half2_rn(make_float2(v.x, v.y));
        __half2 hi = __float22half2_rn(make_float2(v.z, v.w));
        uint2 u;
        u.x = *(uint32_t*)&lo;
        u.y = *(uint32_t*)&hi;
        out[i] = u;
    }
}

// ---------------------------------------------------------------------------
// Weight transpose + fp16 convert:  W[k,n] -> Wt[n*K + k]
// HEADED: input stored [H, K, 64], logical n = h*64 + d
// ---------------------------------------------------------------------------
template<bool HEADED>
__global__ void __launch_bounds__(256)
transpose_h(const float* __restrict__ W, __half* __restrict__ Wt, int K, int N)
{
    __shared__ float tile[32][33];
    const int k0 = blockIdx.x * 32, n0 = blockIdx.y * 32;
    const int tx = threadIdx.x & 31, ty = threadIdx.x >> 5;   // 32 x 8
    #pragma unroll
    for (int r = 0; r < 32; r += 8) {
        const int k = k0 + ty + r, n = n0 + tx;
        float v;
        if (HEADED) v = W[((size_t)(n >> 6) * K + k) * 64 + (n & 63)];
        else        v = W[(size_t)k * N + n];
        tile[ty + r][tx] = v;
    }
    __syncthreads();
    #pragma unroll
    for (int r = 0; r < 32; r += 8) {
        const int n = n0 + ty + r, k = k0 + tx;
        Wt[(size_t)n * K + k] = __float2half_rn(tile[tx][ty + r]);
    }
}

// ---------------------------------------------------------------------------
// FP16 tensor-core GEMM: C[M,N] = A[M,K] @ Bt[N,K]^T  (+ epilogues)
// Block tile 128(m) x 256(n), BK=32, 256 threads, 8 warps of 64x64,
// ldmatrix fragments, cp.async double-buffered smem, padded stride 40 halves.
// EPI: 0 none, 1 +bias+ReLU, 2 +bias+residual(fp32)
// OMODE: 0 fp32 out, 1 fp16 out, 2 both
// ---------------------------------------------------------------------------
#define GSA 40                        // smem row stride in halves (32 + 8 pad)
#define A_HALVES (128 * GSA)          // 5120
#define B_HALVES (256 * GSA)          // 10240
#define GEMM_SMEM_BYTES ((A_HALVES + B_HALVES) * 2 * 2)   // 61440

template<int EPI, int OMODE>
__global__ void __launch_bounds__(256, 1)
hgemm(const __half* __restrict__ A, const __half* __restrict__ Bt,
      const float* __restrict__ bias, const float* __restrict__ res,
      float* __restrict__ Cf, __half* __restrict__ Ct, int N, int K)
{
    extern __shared__ __half smh[];
    const uint32_t sb = smem_u32(smh);

    const int tid  = threadIdx.x;
    const int lane = tid & 31;
    const int g    = lane >> 2;
    const int t    = lane & 3;
    const int warp = tid >> 5;
    const int wm   = (warp & 1) * 64;
    const int wn   = (warp >> 1) * 64;

    const int row0 = blockIdx.y * 128;
    const int col0 = blockIdx.x * 256;

    const uint32_t sA[2] = { sb, sb + A_HALVES * 2 };
    const uint32_t sB[2] = { sb + A_HALVES * 4, sb + A_HALVES * 4 + B_HALVES * 2 };

    // ldmatrix lane offsets
    const int a_row = (lane & 7) + ((lane >> 3) & 1) * 8;  // + wm + 16*mt
    const int a_col = (lane >> 4) * 8;                     // + 16*kc
    const int b_row = (lane & 7) + (lane >> 4) * 8;        // + wn + 16*ntp
    const int b_col = ((lane >> 3) & 1) * 8;               // + 16*kc

    const int nkt = K / 32;

    auto load_tile = [&](int kt, int buf) {
        const int kk = kt * 32;
        #pragma unroll
        for (int i = 0; i < 2; i++) {
            const int c = tid + i * 256, row = c >> 2, k8 = (c & 3) * 8;
            CP_ASYNC16(sA[buf] + (uint32_t)(row * GSA + k8) * 2,
                       A + (size_t)(row0 + row) * K + kk + k8);
        }
        #pragma unroll
        for (int i = 0; i < 4; i++) {
            const int c = tid + i * 256, row = c >> 2, k8 = (c & 3) * 8;
            CP_ASYNC16(sB[buf] + (uint32_t)(row * GSA + k8) * 2,
                       Bt + (size_t)(col0 + row) * K + kk + k8);
        }
        CP_COMMIT();
    };

    float acc[4][8][4];
    #pragma unroll
    for (int mt = 0; mt < 4; mt++)
        #pragma unroll
        for (int nt = 0; nt < 8; nt++)
            #pragma unroll
            for (int i = 0; i < 4; i++) acc[mt][nt][i] = 0.f;

    load_tile(0, 0);

    for (int kt = 0; kt < nkt; kt++) {
        const int buf = kt & 1;
        if (kt + 1 < nkt) {
            load_tile(kt + 1, buf ^ 1);
            CP_WAIT(1);
        } else {
            CP_WAIT(0);
        }
        __syncthreads();

        #pragma unroll
        for (int kc = 0; kc < 2; kc++) {
            uint32_t af[4][4];
            #pragma unroll
            for (int mt = 0; mt < 4; mt++) {
                LDSM4(af[mt][0], af[mt][1], af[mt][2], af[mt][3],
                      sA[buf] + (uint32_t)((wm + mt * 16 + a_row) * GSA + kc * 16 + a_col) * 2);
            }
            uint32_t bf[8][2];
            #pragma unroll
            for (int ntp = 0; ntp < 4; ntp++) {
                LDSM4(bf[2 * ntp][0], bf[2 * ntp][1], bf[2 * ntp + 1][0], bf[2 * ntp + 1][1],
                      sB[buf] + (uint32_t)((wn + ntp * 16 + b_row) * GSA + kc * 16 + b_col) * 2);
            }
            #pragma unroll
            for (int mt = 0; mt < 4; mt++)
                #pragma unroll
                for (int nt = 0; nt < 8; nt++)
                    MMA_F16(acc[mt][nt], af[mt][0], af[mt][1], af[mt][2], af[mt][3],
                            bf[nt][0], bf[nt][1]);
        }
        __syncthreads();
    }

    // ---- epilogue ----
    #pragma unroll
    for (int mt = 0; mt < 4; mt++) {
        #pragma unroll
        for (int nt = 0; nt < 8; nt++) {
            const int r = row0 + wm + mt * 16 + g;
            const int c = col0 + wn + nt * 8 + 2 * t;
            float2 v0 = make_float2(acc[mt][nt][0], acc[mt][nt][1]);
            float2 v1 = make_float2(acc[mt][nt][2], acc[mt][nt][3]);
            if (EPI != 0) {
                const float2 bb = *(const float2*)(bias + c);
                v0.x += bb.x; v0.y += bb.y;
                v1.x += bb.x; v1.y += bb.y;
            }
            if (EPI == 2) {
                const float2 r0v = *(const float2*)(res + (size_t)r * N + c);
                const float2 r1v = *(const float2*)(res + (size_t)(r + 8) * N + c);
                v0.x += r0v.x; v0.y += r0v.y;
                v1.x += r1v.x; v1.y += r1v.y;
            }
            if (EPI == 1) {
                v0.x = fmaxf(v0.x, 0.f); v0.y = fmaxf(v0.y, 0.f);
                v1.x = fmaxf(v1.x, 0.f); v1.y = fmaxf(v1.y, 0.f);
            }
            if (OMODE == 0 || OMODE == 2) {
                *(float2*)(Cf + (size_t)r * N + c) = v0;
                *(float2*)(Cf + (size_t)(r + 8) * N + c) = v1;
            }
            if (OMODE == 1 || OMODE == 2) {
                __half2 h0 = __float22half2_rn(v0);
                __half2 h1 = __float22half2_rn(v1);
                *(__half2*)(Ct + (size_t)r * N + c) = h0;
                *(__half2*)(Ct + (size_t)(r + 8) * N + c) = h1;
            }
        }
    }
}

// ---------------------------------------------------------------------------
// Tensor-core causal flash attention (fp16 mma, fp32 softmax/accum).
// CTA: 128 q rows of one (b,h). 8 warps x 16 rows. Key tiles of 128,
// cp.async double-buffered K/V. scale = E^-0.5 = 1/32.
// smem (halves): Q[128][72] | K0[128][72] | V0[128][72] | K1 | V1
// ---------------------------------------------------------------------------
#define FST 72
#define FT_HALVES (128 * FST)                    // 9216
#define FLASH_SMEM_BYTES (5 * FT_HALVES * 2)     // 92160

__global__ void __launch_bounds__(256, 1)
flash_tc(const __half* __restrict__ Qg, const __half* __restrict__ Kg,
         const __half* __restrict__ Vg, __half* __restrict__ O)
{
    extern __shared__ __half fsm[];
    const uint32_t sb = smem_u32(fsm);

    const int qb = blockIdx.x;           // 0..15
    const int bh = blockIdx.y;           // 0..63
    const int b  = bh >> 4;
    const int h  = bh & 15;

    const int tid  = threadIdx.x;
    const int lane = tid & 31;
    const int g    = lane >> 2;
    const int t    = lane & 3;
    const int w    = tid >> 5;           // warp 0..7 -> q rows [16w, 16w+16)

    const uint32_t QO = 0;
    const uint32_t KO[2] = { FT_HALVES, 3 * FT_HALVES };
    const uint32_t VO[2] = { 2 * FT_HALVES, 4 * FT_HALVES };

    // ---- stage Q tile ----
    {
        #pragma unroll
        for (int i = 0; i < 4; i++) {
            const int c = tid + i * 256;           // 0..1023
            const int row = c >> 3, h8 = (c & 7) * 8;
            const __half* src = Qg + ((size_t)(b * Sz + qb * 128 + row)) * Ez + h * Dz + h8;
            *(uint4*)(fsm + QO + row * FST + h8) = *(const uint4*)src;
        }
    }

    auto load_kv = [&](int kt, int buf) {
        #pragma unroll
        for (int i = 0; i < 4; i++) {
            const int c = tid + i * 256;
            const int row = c >> 3, h8 = (c & 7) * 8;
            const size_t goff = ((size_t)(b * Sz + kt * 128 + row)) * Ez + h * Dz + h8;
            CP_ASYNC16(sb + (KO[buf] + row * FST + h8) * 2, Kg + goff);
            CP_ASYNC16(sb + (VO[buf] + row * FST + h8) * 2, Vg + goff);
        }
        CP_COMMIT();
    };

    load_kv(0, 0);
    __syncthreads();

    // ---- Q fragments (held for whole CTA) ----
    const int a_row = (lane & 7) + ((lane >> 3) & 1) * 8;
    const int a_col = (lane >> 4) * 8;
    uint32_t aq[4][4];
    #pragma unroll
    for (int kc = 0; kc < 4; kc++) {
        LDSM4(aq[kc][0], aq[kc][1], aq[kc][2], aq[kc][3],
              sb + (QO + (w * 16 + a_row) * FST + kc * 16 + a_col) * 2);
    }

    // online softmax state (rows g and g+8 of this thread)
    float mA = -1e30f, mB = -1e30f, lA = 0.f, lB = 0.f;
    float o[8][4];
    #pragma unroll
    for (int i = 0; i < 8; i++)
        #pragma unroll
        for (int j = 0; j < 4; j++) o[i][j] = 0.f;

    const int qrA = qb * 128 + w * 16 + g;
    const int qrB = qrA + 8;

    const int b_row = (lane & 7);           // + 8*nt   (K frags)
    const int b_colq = (lane >> 3) * 8;     // + 32*kcp (K frags)
    const int v_row = (lane >> 3) * 8 + (lane & 7);   // + 32*kcp (V frags, trans)

    const int ntiles = qb + 1;
    for (int kt = 0; kt < ntiles; kt++) {
        const int buf = kt & 1;
        if (kt + 1 < ntiles) {
            load_kv(kt + 1, buf ^ 1);
            CP_WAIT(1);
        } else {
            CP_WAIT(0);
        }
        __syncthreads();

        // ---- S = Q K^T (128 keys) ----
        float s[16][4];
        #pragma unroll
        for (int nt = 0; nt < 16; nt++)
            #pragma unroll
            for (int i = 0; i < 4; i++) s[nt][i] = 0.f;

        #pragma unroll
        for (int nt = 0; nt < 16; nt++) {
            #pragma unroll
            for (int kcp = 0; kcp < 2; kcp++) {
                uint32_t b0, b1, b2, b3;
                LDSM4(b0, b1, b2, b3,
                      sb + (KO[buf] + (nt * 8 + b_row) * FST + kcp * 32 + b_colq) * 2);
                MMA_F16(s[nt], aq[2 * kcp][0], aq[2 * kcp][1], aq[2 * kcp][2], aq[2 * kcp][3], b0, b1);
                MMA_F16(s[nt], aq[2 * kcp + 1][0], aq[2 * kcp + 1][1], aq[2 * kcp + 1][2], aq[2 * kcp + 1][3], b2, b3);
            }
        }

        // ---- scale + causal mask ----
        const float sc = 0.03125f;
        if (kt == qb) {
            #pragma unroll
            for (int nt = 0; nt < 16; nt++) {
                const int key = kt * 128 + nt * 8 + 2 * t;
                s[nt][0] = (key     <= qrA) ? s[nt][0] * sc : -1e30f;
                s[nt][1] = (key + 1 <= qrA) ? s[nt][1] * sc : -1e30f;
                s[nt][2] = (key     <= qrB) ? s[nt][2] * sc : -1e30f;
                s[nt][3] = (key + 1 <= qrB) ? s[nt][3] * sc : -1e30f;
            }
        } else {
            #pragma unroll
            for (int nt = 0; nt < 16; nt++)
                #pragma unroll
                for (int i = 0; i < 4; i++) s[nt][i] *= sc;
        }

        // ---- online softmax ----
        float mxA = -1e30f, mxB = -1e30f;
        #pragma unroll
        for (int nt = 0; nt < 16; nt++) {
            mxA = fmaxf(mxA, fmaxf(s[nt][0], s[nt][1]));
            mxB = fmaxf(mxB, fmaxf(s[nt][2], s[nt][3]));
        }
        mxA = fmaxf(mxA, __shfl_xor_sync(0xffffffffu, mxA, 1));
        mxA = fmaxf(mxA, __shfl_xor_sync(0xffffffffu, mxA, 2));
        mxB = fmaxf(mxB, __shfl_xor_sync(0xffffffffu, mxB, 1));
        mxB = fmaxf(mxB, __shfl_xor_sync(0xffffffffu, mxB, 2));

        const float mAn = fmaxf(mA, mxA);
        const float mBn = fmaxf(mB, mxB);
        const float corrA = __expf(mA - mAn);
        const float corrB = __expf(mB - mBn);
        mA = mAn; mB = mBn;

        float sumA = 0.f, sumB = 0.f;
        uint32_t ph[16][2];
        #pragma unroll
        for (int nt = 0; nt < 16; nt++) {
            const float p0 = __expf(s[nt][0] - mA);
            const float p1 = __expf(s[nt][1] - mA);
            const float p2 = __expf(s[nt][2] - mB);
            const float p3 = __expf(s[nt][3] - mB);
            sumA += p0 + p1; sumB += p2 + p3;
            __half2 hA = __float22half2_rn(make_float2(p0, p1));
            __half2 hB = __float22half2_rn(make_float2(p2, p3));
            ph[nt][0] = *(uint32_t*)&hA;
            ph[nt][1] = *(uint32_t*)&hB;
        }
        sumA += __shfl_xor_sync(0xffffffffu, sumA, 1);
        sumA += __shfl_xor_sync(0xffffffffu, sumA, 2);
        sumB += __shfl_xor_sync(0xffffffffu, sumB, 1);
        sumB += __shfl_xor_sync(0xffffffffu, sumB, 2);
        lA = lA * corrA + sumA;
        lB = lB * corrB + sumB;

        // rescale O
        #pragma unroll
        for (int i = 0; i < 8; i++) {
            o[i][0] *= corrA; o[i][1] *= corrA;
            o[i][2] *= corrB; o[i][3] *= corrB;
        }

        // ---- O += P V ----
        #pragma unroll
        for (int ntd = 0; ntd < 8; ntd++) {
            #pragma unroll
            for (int kcp = 0; kcp < 4; kcp++) {
                uint32_t v0, v1, v2, v3;
                LDSM4T(v0, v1, v2, v3,
                       sb + (VO[buf] + (kcp * 32 + v_row) * FST + ntd * 8) * 2);
                MMA_F16(o[ntd], ph[4 * kcp][0],     ph[4 * kcp][1],
                                 ph[4 * kcp + 1][0], ph[4 * kcp + 1][1], v0, v1);
                MMA_F16(o[ntd], ph[4 * kcp + 2][0], ph[4 * kcp + 2][1],
                                 ph[4 * kcp + 3][0], ph[4 * kcp + 3][1], v2, v3);
            }
        }
        __syncthreads();
    }

    // ---- write O (fp16) ----
    const float invA = 1.f / lA;
    const float invB = 1.f / lB;
    __half* orowA = O + ((size_t)(b * Sz + qrA)) * Ez + h * Dz;
    __half* orowB = O + ((size_t)(b * Sz + qrB)) * Ez + h * Dz;
    #pragma unroll
    for (int ntd = 0; ntd < 8; ntd++) {
        const int c = ntd * 8 + 2 * t;
        __half2 hA = __float22half2_rn(make_float2(o[ntd][0] * invA, o[ntd][1] * invA));
        __half2 hB = __float22half2_rn(make_float2(o[ntd][2] * invB, o[ntd][3] * invB));
        *(__half2*)(orowA + c) = hA;
        *(__half2*)(orowB + c) = hB;
    }
}

// ---------------------------------------------------------------------------
// Launch
// ---------------------------------------------------------------------------
extern "C" void kernel_launch(void* const* d_in, const int* in_sizes, int n_in,
                              void* d_out, int out_size)
{
    const float* x  = (const float*)d_in[0];
    const float* Wq = (const float*)d_in[1];
    const float* Wk = (const float*)d_in[2];
    const float* Wv = (const float*)d_in[3];
    const float* Wo = (const float*)d_in[4];
    const float* bo = (const float*)d_in[5];
    const float* W1 = (const float*)d_in[6];
    const float* b1 = (const float*)d_in[7];
    const float* W2 = (const float*)d_in[8];
    const float* b2 = (const float*)d_in[9];
    float* out = (float*)d_out;

    __half *Qh, *Kh, *Vh, *ATTp, *X1h, *Hh, *xh;
    float  *X1p;
    __half *WqT, *WkT, *WvT, *WoT, *W1T, *W2T;
    cudaGetSymbolAddress((void**)&Qh,   g_Qh);
    cudaGetSymbolAddress((void**)&Kh,   g_Kh);
    cudaGetSymbolAddress((void**)&Vh,   g_Vh);
    cudaGetSymbolAddress((void**)&ATTp, g_ATT);
    cudaGetSymbolAddress((void**)&X1p,  g_X1);
    cudaGetSymbolAddress((void**)&X1h,  g_X1h);
    cudaGetSymbolAddress((void**)&Hh,   g_Hh);
    cudaGetSymbolAddress((void**)&xh,   g_xh);
    cudaGetSymbolAddress((void**)&WqT,  g_WqT);
    cudaGetSymbolAddress((void**)&WkT,  g_WkT);
    cudaGetSymbolAddress((void**)&WvT,  g_WvT);
    cudaGetSymbolAddress((void**)&WoT,  g_WoT);
    cudaGetSymbolAddress((void**)&W1T,  g_W1T);
    cudaGetSymbolAddress((void**)&W2T,  g_W2T);

    cudaFuncSetAttribute(hgemm<0,1>, cudaFuncAttributeMaxDynamicSharedMemorySize, GEMM_SMEM_BYTES);
    cudaFuncSetAttribute(hgemm<2,2>, cudaFuncAttributeMaxDynamicSharedMemorySize, GEMM_SMEM_BYTES);
    cudaFuncSetAttribute(hgemm<1,1>, cudaFuncAttributeMaxDynamicSharedMemorySize, GEMM_SMEM_BYTES);
    cudaFuncSetAttribute(hgemm<2,0>, cudaFuncAttributeMaxDynamicSharedMemorySize, GEMM_SMEM_BYTES);
    cudaFuncSetAttribute(flash_tc,   cudaFuncAttributeMaxDynamicSharedMemorySize, FLASH_SMEM_BYTES);

    const dim3 tblk(256);

    // 0a: x -> fp16
    conv_h_kernel<<<(Mrows * Ez / 4 + 255) / 256, tblk>>>((const float4*)x, (uint2*)xh, Mrows * Ez / 4);

    // 0b: weight transposes (+ fp16 convert), output [N,K]
    transpose_h<true ><<<dim3(Ez / 32, Ez / 32), tblk>>>(Wq, WqT, Ez, Ez);
    transpose_h<true ><<<dim3(Ez / 32, Ez / 32), tblk>>>(Wk, WkT, Ez, Ez);
    transpose_h<true ><<<dim3(Ez / 32, Ez / 32), tblk>>>(Wv, WvT, Ez, Ez);
    transpose_h<false><<<dim3(Ez / 32, Ez / 32), tblk>>>(Wo, WoT, Ez, Ez);
    transpose_h<false><<<dim3(Ez / 32, FF / 32), tblk>>>(W1, W1T, Ez, FF);
    transpose_h<false><<<dim3(FF / 32, Ez / 32), tblk>>>(W2, W2T, FF, Ez);

    const dim3 grid_e(Ez / 256, Mrows / 128);   // (4, 64)
    const dim3 grid_f(FF / 256, Mrows / 128);   // (16, 64)

    // 1-3: QKV projections (fp16 out)
    hgemm<0,1><<<grid_e, tblk, GEMM_SMEM_BYTES>>>(xh, WqT, nullptr, nullptr, nullptr, Qh, Ez, Ez);
    hgemm<0,1><<<grid_e, tblk, GEMM_SMEM_BYTES>>>(xh, WkT, nullptr, nullptr, nullptr, Kh, Ez, Ez);
    hgemm<0,1><<<grid_e, tblk, GEMM_SMEM_BYTES>>>(xh, WvT, nullptr, nullptr, nullptr, Vh, Ez, Ez);

    // 4: tensor-core causal flash attention (fp16 out)
    flash_tc<<<dim3(Sz / 128, Bz * Hz), tblk, FLASH_SMEM_BYTES>>>(Qh, Kh, Vh, ATTp);

    // 5: x1 = attn @ Wo + bo + x  (fp32 + fp16 out)
    hgemm<2,2><<<grid_e, tblk, GEMM_SMEM_BYTES>>>(ATTp, WoT, bo, x, X1p, X1h, Ez, Ez);

    // 6: h = relu(x1 @ W1 + b1)  (fp16 out)
    hgemm<1,1><<<grid_f, tblk, GEMM_SMEM_BYTES>>>(X1h, W1T, b1, nullptr, nullptr, Hh, FF, Ez);

    // 7: out = x1 + h @ W2 + b2  (fp32 out)
    hgemm<2,0><<<grid_e, tblk, GEMM_SMEM_BYTES>>>(Hh, W2T, b2, X1p, out, nullptr, Ez, FF);
}

// round 8
// speedup vs baseline: 7.0119x; 1.0868x over previous
#include <cuda_runtime.h>
#include <cuda_fp16.h>
#include <cstdint>

// Problem constants
#define Bz 4
#define Sz 2048
#define Ez 1024
#define Hz 16
#define Dz 64
#define Mrows (Bz*Sz)          // 8192
#define FF (4*Ez)              // 4096
#define E3 (3*Ez)              // 3072

// ---------------------------------------------------------------------------
// Scratch (allocation-free: __device__ globals)
// ---------------------------------------------------------------------------
__device__ __half g_QKV[(size_t)Mrows*E3];      // fused Q|K|V, row stride 3072
__device__ __half g_ATT[(size_t)Mrows*Ez];
__device__ float  g_X1 [(size_t)Mrows*Ez];      // fp32 residual
__device__ __half g_X1h[(size_t)Mrows*Ez];
__device__ __half g_Hh [(size_t)Mrows*FF];
__device__ __half g_xh [(size_t)Mrows*Ez];
// transposed fp16 weights, layout [N, K]
__device__ __half g_Wqkv[(size_t)E3*Ez];        // rows 0..1023 Q, 1024.. K, 2048.. V
__device__ __half g_WoT[(size_t)Ez*Ez];
__device__ __half g_W1T[(size_t)FF*Ez];
__device__ __half g_W2T[(size_t)Ez*FF];

// ---------------------------------------------------------------------------
// Helpers
// ---------------------------------------------------------------------------
__device__ __forceinline__ uint32_t smem_u32(const void* p) {
    uint32_t a;
    asm("{ .reg .u64 t; cvta.to.shared.u64 t, %1; cvt.u32.u64 %0, t; }"
        : "=r"(a) : "l"(p));
    return a;
}

__device__ __forceinline__ float ex2f(float x) {
    float r;
    asm("ex2.approx.f32 %0, %1;" : "=f"(r) : "f"(x));
    return r;
}

#define CP_ASYNC16(dst, src) \
    asm volatile("cp.async.cg.shared.global [%0], [%1], 16;" :: "r"(dst), "l"(src))
#define CP_COMMIT() asm volatile("cp.async.commit_group;" ::: "memory")
#define CP_WAIT(n)  asm volatile("cp.async.wait_group %0;" :: "n"(n) : "memory")

#define MMA_F16(d, a0_, a1_, a2_, a3_, b0_, b1_)                            \
    asm volatile(                                                           \
        "mma.sync.aligned.m16n8k16.row.col.f32.f16.f16.f32 "                \
        "{%0,%1,%2,%3}, {%4,%5,%6,%7}, {%8,%9}, {%0,%1,%2,%3};"             \
        : "+f"((d)[0]), "+f"((d)[1]), "+f"((d)[2]), "+f"((d)[3])            \
        : "r"(a0_), "r"(a1_), "r"(a2_), "r"(a3_), "r"(b0_), "r"(b1_))

#define LDSM4(r0, r1, r2, r3, addr)                                         \
    asm volatile("ldmatrix.sync.aligned.m8n8.x4.shared.b16 {%0,%1,%2,%3}, [%4];" \
        : "=r"(r0), "=r"(r1), "=r"(r2), "=r"(r3) : "r"(addr))

#define LDSM4T(r0, r1, r2, r3, addr)                                        \
    asm volatile("ldmatrix.sync.aligned.m8n8.x4.trans.shared.b16 {%0,%1,%2,%3}, [%4];" \
        : "=r"(r0), "=r"(r1), "=r"(r2), "=r"(r3) : "r"(addr))

// ---------------------------------------------------------------------------
// fp32 -> fp16 elementwise convert (for x)
// ---------------------------------------------------------------------------
__global__ void __launch_bounds__(256)
conv_h_kernel(const float4* __restrict__ in, uint2* __restrict__ out, int n4)
{
    const int i = blockIdx.x * 256 + threadIdx.x;
    if (i < n4) {
        const float4 v = in[i];
        __half2 lo = __float22half2_rn(make_float2(v.x, v.y));
        __half2 hi = __float22half2_rn(make_float2(v.z, v.w));
        uint2 u;
        u.x = *(uint32_t*)&lo;
        u.y = *(uint32_t*)&hi;
        out[i] = u;
    }
}

// ---------------------------------------------------------------------------
// Weight transpose + fp16 convert
// transpose_h : W[k,n] -> Wt[n*K + k]
// transpose_h3: headed [H,K,64] Wq/Wk/Wv -> combined [3E, K] via blockIdx.z
// ---------------------------------------------------------------------------
__global__ void __launch_bounds__(256)
transpose_h(const float* __restrict__ W, __half* __restrict__ Wt, int K, int N)
{
    __shared__ float tile[32][33];
    const int k0 = blockIdx.x * 32, n0 = blockIdx.y * 32;
    const int tx = threadIdx.x & 31, ty = threadIdx.x >> 5;
    #pragma unroll
    for (int r = 0; r < 32; r += 8)
        tile[ty + r][tx] = W[(size_t)(k0 + ty + r) * N + n0 + tx];
    __syncthreads();
    #pragma unroll
    for (int r = 0; r < 32; r += 8)
        Wt[(size_t)(n0 + ty + r) * K + k0 + tx] = __float2half_rn(tile[tx][ty + r]);
}

__global__ void __launch_bounds__(256)
transpose_h3(const float* __restrict__ Wq, const float* __restrict__ Wk,
             const float* __restrict__ Wv, __half* __restrict__ Wt)
{
    __shared__ float tile[32][33];
    const int K = Ez;
    const float* W = (blockIdx.z == 0) ? Wq : (blockIdx.z == 1) ? Wk : Wv;
    const int k0 = blockIdx.x * 32, n0 = blockIdx.y * 32;
    const int tx = threadIdx.x & 31, ty = threadIdx.x >> 5;
    #pragma unroll
    for (int r = 0; r < 32; r += 8) {
        const int k = k0 + ty + r, n = n0 + tx;
        tile[ty + r][tx] = W[((size_t)(n >> 6) * K + k) * 64 + (n & 63)];
    }
    __syncthreads();
    const size_t nbase = (size_t)blockIdx.z * Ez;
    #pragma unroll
    for (int r = 0; r < 32; r += 8) {
        const int n = n0 + ty + r, k = k0 + tx;
        Wt[(nbase + n) * K + k] = __float2half_rn(tile[tx][ty + r]);
    }
}

// ---------------------------------------------------------------------------
// FP16 tensor-core GEMM: C[M,N] = A[M,K] @ Bt[N,K]^T  (+ epilogues)
// Block tile 128(m) x 256(n), BK=32, 256 threads, 8 warps of 64x64,
// ldmatrix fragments, 3-stage cp.async pipeline, ONE sync per k-iter.
// EPI: 0 none, 1 +bias+ReLU, 2 +bias+residual(fp32)
// OMODE: 0 fp32 out, 1 fp16 out, 2 both
// ---------------------------------------------------------------------------
#define GSA 40                         // smem row stride in halves (32 + 8 pad)
#define A_HALVES (128 * GSA)           // 5120
#define B_HALVES (256 * GSA)           // 10240
#define STG_HALVES (A_HALVES + B_HALVES)
#define GEMM_SMEM_BYTES (3 * STG_HALVES * 2)   // 92160

template<int EPI, int OMODE>
__global__ void __launch_bounds__(256, 1)
hgemm(const __half* __restrict__ A, const __half* __restrict__ Bt,
      const float* __restrict__ bias, const float* __restrict__ res,
      float* __restrict__ Cf, __half* __restrict__ Ct, int N, int K)
{
    extern __shared__ __half smh[];
    const uint32_t sb = smem_u32(smh);

    const int tid  = threadIdx.x;
    const int lane = tid & 31;
    const int g    = lane >> 2;
    const int t    = lane & 3;
    const int warp = tid >> 5;
    const int wm   = (warp & 1) * 64;
    const int wn   = (warp >> 1) * 64;

    const int row0 = blockIdx.y * 128;
    const int col0 = blockIdx.x * 256;

    // ldmatrix lane offsets
    const int a_row = (lane & 7) + ((lane >> 3) & 1) * 8;
    const int a_col = (lane >> 4) * 8;
    const int b_row = (lane & 7) + (lane >> 4) * 8;
    const int b_col = ((lane >> 3) & 1) * 8;

    const int nkt = K / 32;

    auto load_tile = [&](int kt, int stg) {
        const int kk = kt * 32;
        const uint32_t base = sb + (uint32_t)stg * STG_HALVES * 2;
        #pragma unroll
        for (int i = 0; i < 2; i++) {
            const int c = tid + i * 256, row = c >> 2, k8 = (c & 3) * 8;
            CP_ASYNC16(base + (uint32_t)(row * GSA + k8) * 2,
                       A + (size_t)(row0 + row) * K + kk + k8);
        }
        #pragma unroll
        for (int i = 0; i < 4; i++) {
            const int c = tid + i * 256, row = c >> 2, k8 = (c & 3) * 8;
            CP_ASYNC16(base + (uint32_t)(A_HALVES + row * GSA + k8) * 2,
                       Bt + (size_t)(col0 + row) * K + kk + k8);
        }
        CP_COMMIT();
    };

    float acc[4][8][4];
    #pragma unroll
    for (int mt = 0; mt < 4; mt++)
        #pragma unroll
        for (int nt = 0; nt < 8; nt++)
            #pragma unroll
            for (int i = 0; i < 4; i++) acc[mt][nt][i] = 0.f;

    load_tile(0, 0);
    load_tile(1, 1);

    int stg = 0;
    for (int kt = 0; kt < nkt; kt++) {
        CP_WAIT(1);
        __syncthreads();
        if (kt + 2 < nkt) load_tile(kt + 2, (stg + 2) % 3);

        const uint32_t sAb = sb + (uint32_t)stg * STG_HALVES * 2;
        const uint32_t sBb = sAb + (uint32_t)A_HALVES * 2;

        #pragma unroll
        for (int kc = 0; kc < 2; kc++) {
            uint32_t af[4][4];
            #pragma unroll
            for (int mt = 0; mt < 4; mt++) {
                LDSM4(af[mt][0], af[mt][1], af[mt][2], af[mt][3],
                      sAb + (uint32_t)((wm + mt * 16 + a_row) * GSA + kc * 16 + a_col) * 2);
            }
            uint32_t bf[8][2];
            #pragma unroll
            for (int ntp = 0; ntp < 4; ntp++) {
                LDSM4(bf[2 * ntp][0], bf[2 * ntp][1], bf[2 * ntp + 1][0], bf[2 * ntp + 1][1],
                      sBb + (uint32_t)((wn + ntp * 16 + b_row) * GSA + kc * 16 + b_col) * 2);
            }
            #pragma unroll
            for (int mt = 0; mt < 4; mt++)
                #pragma unroll
                for (int nt = 0; nt < 8; nt++)
                    MMA_F16(acc[mt][nt], af[mt][0], af[mt][1], af[mt][2], af[mt][3],
                            bf[nt][0], bf[nt][1]);
        }
        stg = (stg + 1) % 3;
    }

    // ---- epilogue ----
    #pragma unroll
    for (int mt = 0; mt < 4; mt++) {
        #pragma unroll
        for (int nt = 0; nt < 8; nt++) {
            const int r = row0 + wm + mt * 16 + g;
            const int c = col0 + wn + nt * 8 + 2 * t;
            float2 v0 = make_float2(acc[mt][nt][0], acc[mt][nt][1]);
            float2 v1 = make_float2(acc[mt][nt][2], acc[mt][nt][3]);
            if (EPI != 0) {
                const float2 bb = *(const float2*)(bias + c);
                v0.x += bb.x; v0.y += bb.y;
                v1.x += bb.x; v1.y += bb.y;
            }
            if (EPI == 2) {
                const float2 r0v = *(const float2*)(res + (size_t)r * N + c);
                const float2 r1v = *(const float2*)(res + (size_t)(r + 8) * N + c);
                v0.x += r0v.x; v0.y += r0v.y;
                v1.x += r1v.x; v1.y += r1v.y;
            }
            if (EPI == 1) {
                v0.x = fmaxf(v0.x, 0.f); v0.y = fmaxf(v0.y, 0.f);
                v1.x = fmaxf(v1.x, 0.f); v1.y = fmaxf(v1.y, 0.f);
            }
            if (OMODE == 0 || OMODE == 2) {
                *(float2*)(Cf + (size_t)r * N + c) = v0;
                *(float2*)(Cf + (size_t)(r + 8) * N + c) = v1;
            }
            if (OMODE == 1 || OMODE == 2) {
                __half2 h0 = __float22half2_rn(v0);
                __half2 h1 = __float22half2_rn(v1);
                *(__half2*)(Ct + (size_t)r * N + c) = h0;
                *(__half2*)(Ct + (size_t)(r + 8) * N + c) = h1;
            }
        }
    }
}

// ---------------------------------------------------------------------------
// Tensor-core causal flash attention (fp16 mma, fp32 softmax/accum).
// Q/K/V read from fused QKV buffer (row stride 3072). Scale folded into exp2:
// p = ex2((s - m) * (E^-0.5 * log2 e)). Single sync per key tile.
// ---------------------------------------------------------------------------
#define FST 72
#define FT_HALVES (128 * FST)                    // 9216
#define FLASH_SMEM_BYTES (5 * FT_HALVES * 2)     // 92160
#define KL2 0.045084402f                          // (1/32) * log2(e)

__global__ void __launch_bounds__(256, 1)
flash_tc(const __half* __restrict__ QKV, __half* __restrict__ O)
{
    extern __shared__ __half fsm[];
    const uint32_t sb = smem_u32(fsm);

    const int qb = blockIdx.x;           // 0..15
    const int bh = blockIdx.y;           // 0..63
    const int b  = bh >> 4;
    const int h  = bh & 15;

    const int tid  = threadIdx.x;
    const int lane = tid & 31;
    const int g    = lane >> 2;
    const int t    = lane & 3;
    const int w    = tid >> 5;

    const __half* Qg = QKV + (size_t)h * Dz;
    const __half* Kg = QKV + Ez + (size_t)h * Dz;
    const __half* Vg = QKV + 2 * Ez + (size_t)h * Dz;

    const uint32_t QO = 0;
    const uint32_t KO[2] = { FT_HALVES, 3 * FT_HALVES };
    const uint32_t VO[2] = { 2 * FT_HALVES, 4 * FT_HALVES };

    // ---- stage Q tile (plain stores) ----
    #pragma unroll
    for (int i = 0; i < 4; i++) {
        const int c = tid + i * 256;
        const int row = c >> 3, h8 = (c & 7) * 8;
        const __half* src = Qg + ((size_t)(b * Sz + qb * 128 + row)) * E3 + h8;
        *(uint4*)(fsm + QO + row * FST + h8) = *(const uint4*)src;
    }

    auto load_kv = [&](int kt, int buf) {
        #pragma unroll
        for (int i = 0; i < 4; i++) {
            const int c = tid + i * 256;
            const int row = c >> 3, h8 = (c & 7) * 8;
            const size_t roff = ((size_t)(b * Sz + kt * 128 + row)) * E3 + h8;
            CP_ASYNC16(sb + (KO[buf] + row * FST + h8) * 2, Kg + roff);
            CP_ASYNC16(sb + (VO[buf] + row * FST + h8) * 2, Vg + roff);
        }
        CP_COMMIT();
    };

    load_kv(0, 0);
    __syncthreads();

    // ---- Q fragments ----
    const int a_row = (lane & 7) + ((lane >> 3) & 1) * 8;
    const int a_col = (lane >> 4) * 8;
    uint32_t aq[4][4];
    #pragma unroll
    for (int kc = 0; kc < 4; kc++) {
        LDSM4(aq[kc][0], aq[kc][1], aq[kc][2], aq[kc][3],
              sb + (QO + (w * 16 + a_row) * FST + kc * 16 + a_col) * 2);
    }

    float mA = -1e30f, mB = -1e30f, lA = 0.f, lB = 0.f;
    float o[8][4];
    #pragma unroll
    for (int i = 0; i < 8; i++)
        #pragma unroll
        for (int j = 0; j < 4; j++) o[i][j] = 0.f;

    const int qrA = qb * 128 + w * 16 + g;
    const int qrB = qrA + 8;

    const int b_row  = (lane & 7);
    const int b_colq = (lane >> 3) * 8;
    const int v_row  = (lane >> 3) * 8 + (lane & 7);

    const int ntiles = qb + 1;
    for (int kt = 0; kt < ntiles; kt++) {
        const int buf = kt & 1;
        CP_WAIT(0);
        __syncthreads();
        if (kt + 1 < ntiles) load_kv(kt + 1, buf ^ 1);

        // ---- S = Q K^T ----
        float s[16][4];
        #pragma unroll
        for (int nt = 0; nt < 16; nt++)
            #pragma unroll
            for (int i = 0; i < 4; i++) s[nt][i] = 0.f;

        #pragma unroll
        for (int nt = 0; nt < 16; nt++) {
            #pragma unroll
            for (int kcp = 0; kcp < 2; kcp++) {
                uint32_t b0, b1, b2, b3;
                LDSM4(b0, b1, b2, b3,
                      sb + (KO[buf] + (nt * 8 + b_row) * FST + kcp * 32 + b_colq) * 2);
                MMA_F16(s[nt], aq[2 * kcp][0], aq[2 * kcp][1], aq[2 * kcp][2], aq[2 * kcp][3], b0, b1);
                MMA_F16(s[nt], aq[2 * kcp + 1][0], aq[2 * kcp + 1][1], aq[2 * kcp + 1][2], aq[2 * kcp + 1][3], b2, b3);
            }
        }

        // ---- causal mask (raw scores; scale folded into exp2) ----
        if (kt == qb) {
            #pragma unroll
            for (int nt = 0; nt < 16; nt++) {
                const int key = kt * 128 + nt * 8 + 2 * t;
                if (key     > qrA) s[nt][0] = -1e30f;
                if (key + 1 > qrA) s[nt][1] = -1e30f;
                if (key     > qrB) s[nt][2] = -1e30f;
                if (key + 1 > qrB) s[nt][3] = -1e30f;
            }
        }

        // ---- online softmax ----
        float mxA = -1e30f, mxB = -1e30f;
        #pragma unroll
        for (int nt = 0; nt < 16; nt++) {
            mxA = fmaxf(mxA, fmaxf(s[nt][0], s[nt][1]));
            mxB = fmaxf(mxB, fmaxf(s[nt][2], s[nt][3]));
        }
        mxA = fmaxf(mxA, __shfl_xor_sync(0xffffffffu, mxA, 1));
        mxA = fmaxf(mxA, __shfl_xor_sync(0xffffffffu, mxA, 2));
        mxB = fmaxf(mxB, __shfl_xor_sync(0xffffffffu, mxB, 1));
        mxB = fmaxf(mxB, __shfl_xor_sync(0xffffffffu, mxB, 2));

        const float mAn = fmaxf(mA, mxA);
        const float mBn = fmaxf(mB, mxB);
        const float corrA = ex2f((mA - mAn) * KL2);
        const float corrB = ex2f((mB - mBn) * KL2);
        mA = mAn; mB = mBn;

        float sumA = 0.f, sumB = 0.f;
        uint32_t ph[16][2];
        #pragma unroll
        for (int nt = 0; nt < 16; nt++) {
            const float p0 = ex2f((s[nt][0] - mA) * KL2);
            const float p1 = ex2f((s[nt][1] - mA) * KL2);
            const float p2 = ex2f((s[nt][2] - mB) * KL2);
            const float p3 = ex2f((s[nt][3] - mB) * KL2);
            sumA += p0 + p1; sumB += p2 + p3;
            __half2 hA = __float22half2_rn(make_float2(p0, p1));
            __half2 hB = __float22half2_rn(make_float2(p2, p3));
            ph[nt][0] = *(uint32_t*)&hA;
            ph[nt][1] = *(uint32_t*)&hB;
        }
        sumA += __shfl_xor_sync(0xffffffffu, sumA, 1);
        sumA += __shfl_xor_sync(0xffffffffu, sumA, 2);
        sumB += __shfl_xor_sync(0xffffffffu, sumB, 1);
        sumB += __shfl_xor_sync(0xffffffffu, sumB, 2);
        lA = lA * corrA + sumA;
        lB = lB * corrB + sumB;

        #pragma unroll
        for (int i = 0; i < 8; i++) {
            o[i][0] *= corrA; o[i][1] *= corrA;
            o[i][2] *= corrB; o[i][3] *= corrB;
        }

        // ---- O += P V ----
        #pragma unroll
        for (int ntd = 0; ntd < 8; ntd++) {
            #pragma unroll
            for (int kcp = 0; kcp < 4; kcp++) {
                uint32_t v0, v1, v2, v3;
                LDSM4T(v0, v1, v2, v3,
                       sb + (VO[buf] + (kcp * 32 + v_row) * FST + ntd * 8) * 2);
                MMA_F16(o[ntd], ph[4 * kcp][0],     ph[4 * kcp][1],
                                 ph[4 * kcp + 1][0], ph[4 * kcp + 1][1], v0, v1);
                MMA_F16(o[ntd], ph[4 * kcp + 2][0], ph[4 * kcp + 2][1],
                                 ph[4 * kcp + 3][0], ph[4 * kcp + 3][1], v2, v3);
            }
        }
    }

    // ---- write O (fp16, row stride Ez) ----
    const float invA = 1.f / lA;
    const float invB = 1.f / lB;
    __half* orowA = O + ((size_t)(b * Sz + qrA)) * Ez + h * Dz;
    __half* orowB = O + ((size_t)(b * Sz + qrB)) * Ez + h * Dz;
    #pragma unroll
    for (int ntd = 0; ntd < 8; ntd++) {
        const int c = ntd * 8 + 2 * t;
        __half2 hA = __float22half2_rn(make_float2(o[ntd][0] * invA, o[ntd][1] * invA));
        __half2 hB = __float22half2_rn(make_float2(o[ntd][2] * invB, o[ntd][3] * invB));
        *(__half2*)(orowA + c) = hA;
        *(__half2*)(orowB + c) = hB;
    }
}

// ---------------------------------------------------------------------------
// Launch
// ---------------------------------------------------------------------------
extern "C" void kernel_launch(void* const* d_in, const int* in_sizes, int n_in,
                              void* d_out, int out_size)
{
    const float* x  = (const float*)d_in[0];
    const float* Wq = (const float*)d_in[1];
    const float* Wk = (const float*)d_in[2];
    const float* Wv = (const float*)d_in[3];
    const float* Wo = (const float*)d_in[4];
    const float* bo = (const float*)d_in[5];
    const float* W1 = (const float*)d_in[6];
    const float* b1 = (const float*)d_in[7];
    const float* W2 = (const float*)d_in[8];
    const float* b2 = (const float*)d_in[9];
    float* out = (float*)d_out;

    __half *QKVp, *ATTp, *X1h, *Hh, *xh;
    float  *X1p;
    __half *WqkvT, *WoT, *W1T, *W2T;
    cudaGetSymbolAddress((void**)&QKVp,  g_QKV);
    cudaGetSymbolAddress((void**)&ATTp,  g_ATT);
    cudaGetSymbolAddress((void**)&X1p,   g_X1);
    cudaGetSymbolAddress((void**)&X1h,   g_X1h);
    cudaGetSymbolAddress((void**)&Hh,    g_Hh);
    cudaGetSymbolAddress((void**)&xh,    g_xh);
    cudaGetSymbolAddress((void**)&WqkvT, g_Wqkv);
    cudaGetSymbolAddress((void**)&WoT,   g_WoT);
    cudaGetSymbolAddress((void**)&W1T,   g_W1T);
    cudaGetSymbolAddress((void**)&W2T,   g_W2T);

    cudaFuncSetAttribute(hgemm<0,1>, cudaFuncAttributeMaxDynamicSharedMemorySize, GEMM_SMEM_BYTES);
    cudaFuncSetAttribute(hgemm<2,2>, cudaFuncAttributeMaxDynamicSharedMemorySize, GEMM_SMEM_BYTES);
    cudaFuncSetAttribute(hgemm<1,1>, cudaFuncAttributeMaxDynamicSharedMemorySize, GEMM_SMEM_BYTES);
    cudaFuncSetAttribute(hgemm<2,0>, cudaFuncAttributeMaxDynamicSharedMemorySize, GEMM_SMEM_BYTES);
    cudaFuncSetAttribute(flash_tc,   cudaFuncAttributeMaxDynamicSharedMemorySize, FLASH_SMEM_BYTES);

    const dim3 tblk(256);

    // 0a: x -> fp16
    conv_h_kernel<<<(Mrows * Ez / 4 + 255) / 256, tblk>>>((const float4*)x, (uint2*)xh, Mrows * Ez / 4);

    // 0b: weight transposes (+ fp16 convert), output [N,K]
    transpose_h3<<<dim3(Ez / 32, Ez / 32, 3), tblk>>>(Wq, Wk, Wv, WqkvT);
    transpose_h <<<dim3(Ez / 32, Ez / 32), tblk>>>(Wo, WoT, Ez, Ez);
    transpose_h <<<dim3(Ez / 32, FF / 32), tblk>>>(W1, W1T, Ez, FF);
    transpose_h <<<dim3(FF / 32, Ez / 32), tblk>>>(W2, W2T, FF, Ez);

    const dim3 grid_qkv(E3 / 256, Mrows / 128);  // (12, 64)
    const dim3 grid_e(Ez / 256, Mrows / 128);    // (4, 64)
    const dim3 grid_f(FF / 256, Mrows / 128);    // (16, 64)

    // 1: fused QKV projection (fp16 out, row stride 3072)
    hgemm<0,1><<<grid_qkv, tblk, GEMM_SMEM_BYTES>>>(xh, WqkvT, nullptr, nullptr, nullptr, QKVp, E3, Ez);

    // 2: tensor-core causal flash attention (fp16 out)
    flash_tc<<<dim3(Sz / 128, Bz * Hz), tblk, FLASH_SMEM_BYTES>>>(QKVp, ATTp);

    // 3: x1 = attn @ Wo + bo + x  (fp32 + fp16 out)
    hgemm<2,2><<<grid_e, tblk, GEMM_SMEM_BYTES>>>(ATTp, WoT, bo, x, X1p, X1h, Ez, Ez);

    // 4: h = relu(x1 @ W1 + b1)  (fp16 out)
    hgemm<1,1><<<grid_f, tblk, GEMM_SMEM_BYTES>>>(X1h, W1T, b1, nullptr, nullptr, Hh, FF, Ez);

    // 5: out = x1 + h @ W2 + b2  (fp32 out)
    hgemm<2,0><<<grid_e, tblk, GEMM_SMEM_BYTES>>>(Hh, W2T, b2, X1p, out, nullptr, Ez, FF);
}